// round 4
// baseline (speedup 1.0000x reference)
#include <cuda_runtime.h>
#include <math.h>

// Problem constants
#define BB 8
#define SS 896          // sequence length S = 512 + 384
#define LX 512
#define DD 1024
#define MTOT (BB*SS)    // 7168 rows
#define NH 16
#define HD 64
#define FFD 4096
#define NLAYERS 4

// Scratch (allocation-free: __device__ globals)
__device__ float g_tgt[MTOT*DD];     // activations
__device__ float g_big[MTOT*FFD];    // qkv (3072 wide) / ff intermediate (4096 wide) / o-proj out
__device__ float g_mid[MTOT*DD];     // attn concat out / ff2 out

// ---------------------------------------------------------------------------
// Prep: build tgt = [ rms(x)[...,1:] @ Wn^T + bn + PE(t) ;  rms(w) @ Wc^T + bc + PE(pos) ]
// ---------------------------------------------------------------------------
__global__ void prep_kernel(const float* __restrict__ x, const float* __restrict__ w,
                            const float* __restrict__ Wn, const float* __restrict__ bn,
                            const float* __restrict__ Wc, const float* __restrict__ bc,
                            float* __restrict__ tgt) {
    const int row = blockIdx.x;          // 0..7167
    const int b = row / SS, s = row % SS;
    const int tid = threadIdx.x;         // 256 threads
    __shared__ float f[64];
    __shared__ float sh_t;
    const float rs = 0.9999500037496877f;   // 1/sqrt(1 + 1e-4)
    const float cdiv = -0.0067458547646309937f; // -log(1000)/1024

    if (s < LX) {
        if (tid < 64) {
            float v = x[((size_t)b*LX + s)*64 + tid];
            if (isnan(v)) v = 0.f;
            if (tid == 0) sh_t = v;
            v *= rs;
            v = fminf(5.f, fmaxf(-5.f, v));
            f[tid] = v;
        }
        __syncthreads();
        const float t = sh_t;
        #pragma unroll
        for (int it = 0; it < 4; it++) {
            const int d = tid + it*256;
            float acc = bn[d];
            const float* wr = Wn + (size_t)d*63;
            #pragma unroll 7
            for (int k = 0; k < 63; k++) acc += f[k+1]*wr[k];
            const int i = d >> 1;
            const float div = expf((float)i * cdiv);
            const float ang = t * div;
            acc += (d & 1) ? cosf(ang) : sinf(ang);
            tgt[(size_t)row*DD + d] = acc;
        }
    } else {
        const int j = s - LX;            // 0..383
        if (tid < 6) {
            float v = w[((size_t)b*384 + j)*6 + tid];
            if (isnan(v)) v = 0.f;
            v *= rs;
            v = fminf(5.f, fmaxf(-5.f, v));
            f[tid] = v;
        }
        __syncthreads();
        const float pos = (float)s;
        #pragma unroll
        for (int it = 0; it < 4; it++) {
            const int d = tid + it*256;
            float acc = bc[d];
            const float* wr = Wc + (size_t)d*6;
            #pragma unroll
            for (int k = 0; k < 6; k++) acc += f[k]*wr[k];
            const int i = d >> 1;
            const float div = expf((float)i * cdiv);
            const float ang = pos * div;
            acc += (d & 1) ? cosf(ang) : sinf(ang);
            tgt[(size_t)row*DD + d] = acc;
        }
    }
}

// ---------------------------------------------------------------------------
// fp32 NT GEMM: C[M,N] = A[M,K] @ W[N,K]^T + bias[N], optional exact GELU
// 128x128 tile, BK=8, 256 threads, 8x8 micro-tile. All dims multiples of tile.
// ---------------------------------------------------------------------------
template<bool GELU>
__global__ __launch_bounds__(256) void gemm_nt_bias(
        const float* __restrict__ A, const float* __restrict__ W,
        const float* __restrict__ bias, float* __restrict__ C,
        int M, int N, int K) {
    __shared__ float As[8][128];
    __shared__ float Bs[8][128];
    const int tid = threadIdx.x;
    const int m0 = blockIdx.y * 128;
    const int n0 = blockIdx.x * 128;
    const int tx = tid & 15, ty = tid >> 4;
    const int lr = tid >> 1;         // 0..127
    const int lk = (tid & 1) * 4;    // 0 or 4
    const float* Ap = A + (size_t)(m0 + lr) * K + lk;
    const float* Wp = W + (size_t)(n0 + lr) * K + lk;
    float acc[8][8] = {};
    for (int k0 = 0; k0 < K; k0 += 8) {
        float4 a4 = *(const float4*)(Ap + k0);
        float4 b4 = *(const float4*)(Wp + k0);
        As[lk+0][lr] = a4.x; As[lk+1][lr] = a4.y; As[lk+2][lr] = a4.z; As[lk+3][lr] = a4.w;
        Bs[lk+0][lr] = b4.x; Bs[lk+1][lr] = b4.y; Bs[lk+2][lr] = b4.z; Bs[lk+3][lr] = b4.w;
        __syncthreads();
        #pragma unroll
        for (int k = 0; k < 8; k++) {
            float a[8], b[8];
            #pragma unroll
            for (int i = 0; i < 8; i++) a[i] = As[k][ty*8+i];
            #pragma unroll
            for (int j = 0; j < 8; j++) b[j] = Bs[k][tx*8+j];
            #pragma unroll
            for (int i = 0; i < 8; i++)
                #pragma unroll
                for (int j = 0; j < 8; j++)
                    acc[i][j] += a[i]*b[j];
        }
        __syncthreads();
    }
    #pragma unroll
    for (int i = 0; i < 8; i++) {
        const int m = m0 + ty*8 + i;
        #pragma unroll
        for (int j = 0; j < 8; j++) {
            const int n = n0 + tx*8 + j;
            float v = acc[i][j] + bias[n];
            if (GELU) v = 0.5f * v * (1.0f + erff(v * 0.70710678118654752f));
            C[(size_t)m*N + n] = v;
        }
    }
}

// ---------------------------------------------------------------------------
// Flash attention, fp32. qkv layout: [B*S, 3072] = [q(0..1023) k(1024..2047) v(2048..3071)]
// Mask: cols < 512 always visible; cols >= 512 causal (col <= row).
// grid(7, B*NH), block 128; thread owns one q row (head dim 64 in regs).
// ---------------------------------------------------------------------------
__global__ __launch_bounds__(128) void flash_attn_kernel(
        const float* __restrict__ qkv, float* __restrict__ out) {
    const int q0 = blockIdx.x * 128;
    const int bh = blockIdx.y;
    const int b = bh >> 4, h = bh & 15;
    const int tid = threadIdx.x;
    const int qrow = q0 + tid;
    const float* base = qkv + (size_t)b * SS * 3072;
    __shared__ float Ks[32*64];
    __shared__ float Vs[32*64];
    __shared__ float Ps[32*128];
    float q[64], acc[64];
    {
        const float* qp = base + (size_t)qrow*3072 + h*64;
        #pragma unroll
        for (int i = 0; i < 16; i++) {
            float4 v = *(const float4*)(qp + i*4);
            q[i*4+0]=v.x; q[i*4+1]=v.y; q[i*4+2]=v.z; q[i*4+3]=v.w;
        }
    }
    #pragma unroll
    for (int d = 0; d < 64; d++) acc[d] = 0.f;
    float mval = -1e30f, lsum = 0.f;
    int kt_end = (q0 + 127) / 32 + 1;
    if (kt_end < 16) kt_end = 16;       // x-region (cols 0..511) always visible
    for (int kt = 0; kt < kt_end; kt++) {
        const int c0 = kt * 32;
        __syncthreads();
        #pragma unroll
        for (int i = 0; i < 4; i++) {
            const int slot = i*128 + tid;       // 0..511 float4 slots
            const int row = slot >> 4, col4 = slot & 15;
            const float* kp = base + (size_t)(c0+row)*3072 + 1024 + h*64 + col4*4;
            ((float4*)Ks)[slot] = *(const float4*)kp;
            ((float4*)Vs)[slot] = *(const float4*)(kp + 1024);
        }
        __syncthreads();
        const int jlim = (c0 + 32 <= LX) ? 32 : (qrow - c0 + 1);
        float tmax = -1e30f;
        #pragma unroll 4
        for (int j = 0; j < 32; j++) {
            float s = 0.f;
            const float* kr = &Ks[j*64];
            #pragma unroll
            for (int d = 0; d < 64; d++) s += q[d]*kr[d];
            s *= 0.125f;                 // 1/sqrt(64)
            if (j >= jlim) s = -1e30f;
            Ps[j*128 + tid] = s;
            tmax = fmaxf(tmax, s);
        }
        if (tmax > -1e29f) {             // at least one visible key in tile
            const float mnew = fmaxf(mval, tmax);
            const float alpha = expf(mval - mnew);
            lsum *= alpha;
            #pragma unroll
            for (int d = 0; d < 64; d++) acc[d] *= alpha;
            #pragma unroll 2
            for (int j = 0; j < 32; j++) {
                const float e = expf(Ps[j*128 + tid] - mnew);
                lsum += e;
                const float* vr = &Vs[j*64];
                #pragma unroll
                for (int d = 0; d < 64; d++) acc[d] += e*vr[d];
            }
            mval = mnew;
        }
    }
    const float inv = 1.f / lsum;
    float* op = out + (size_t)(b*SS + qrow)*DD + h*64;
    #pragma unroll
    for (int i = 0; i < 16; i++) {
        float4 v;
        v.x = acc[i*4+0]*inv; v.y = acc[i*4+1]*inv;
        v.z = acc[i*4+2]*inv; v.w = acc[i*4+3]*inv;
        *(float4*)(op + i*4) = v;
    }
}

// ---------------------------------------------------------------------------
// x = LayerNorm(x + r) * g + b   (in-place on x), one block per row, D=1024
// ---------------------------------------------------------------------------
__global__ __launch_bounds__(256) void add_ln_kernel(
        float* __restrict__ x, const float* __restrict__ r,
        const float* __restrict__ g, const float* __restrict__ bt) {
    const int row = blockIdx.x;
    const int tid = threadIdx.x;
    const size_t off = (size_t)row*DD + tid*4;
    float4 xv = *(float4*)(x + off);
    const float4 rv = *(const float4*)(r + off);
    xv.x += rv.x; xv.y += rv.y; xv.z += rv.z; xv.w += rv.w;
    float s  = xv.x + xv.y + xv.z + xv.w;
    float s2 = xv.x*xv.x + xv.y*xv.y + xv.z*xv.z + xv.w*xv.w;
    __shared__ float sh[16];
    #pragma unroll
    for (int o = 16; o; o >>= 1) {
        s  += __shfl_xor_sync(0xffffffffu, s,  o);
        s2 += __shfl_xor_sync(0xffffffffu, s2, o);
    }
    const int warp = tid >> 5, lane = tid & 31;
    if (lane == 0) { sh[warp] = s; sh[warp+8] = s2; }
    __syncthreads();
    if (tid < 32) {
        float a  = (lane < 8) ? sh[lane]   : 0.f;
        float a2 = (lane < 8) ? sh[lane+8] : 0.f;
        #pragma unroll
        for (int o = 4; o; o >>= 1) {
            a  += __shfl_xor_sync(0xffffffffu, a,  o);
            a2 += __shfl_xor_sync(0xffffffffu, a2, o);
        }
        if (lane == 0) { sh[0] = a; sh[1] = a2; }
    }
    __syncthreads();
    const float mean = sh[0] * (1.f/1024.f);
    const float var  = sh[1] * (1.f/1024.f) - mean*mean;
    const float rstd = 1.f / sqrtf(var + 1e-5f);
    const float4 gv = *(const float4*)(g  + tid*4);
    const float4 bv = *(const float4*)(bt + tid*4);
    float4 o;
    o.x = (xv.x - mean)*rstd*gv.x + bv.x;
    o.y = (xv.y - mean)*rstd*gv.y + bv.y;
    o.z = (xv.z - mean)*rstd*gv.z + bv.z;
    o.w = (xv.w - mean)*rstd*gv.w + bv.w;
    *(float4*)(x + off) = o;
}

// ---------------------------------------------------------------------------
// loss = mean( (tgt[:,-1] @ W_ham^T + b_ham - (y - w_last))^2 )  over 8*144
// ---------------------------------------------------------------------------
__global__ void loss_kernel(const float* __restrict__ tgt, const float* __restrict__ Wh,
                            const float* __restrict__ bh, const float* __restrict__ y,
                            const float* __restrict__ w, float* __restrict__ out) {
    const int tid = threadIdx.x;   // 256
    float local = 0.f;
    for (int e = tid; e < 8*144; e += 256) {
        const int b = e / 144, j = e % 144;
        const float4* trow = (const float4*)(tgt + ((size_t)b*SS + SS-1)*DD);
        const float4* wr   = (const float4*)(Wh + (size_t)j*DD);
        float acc = bh[j];
        for (int k = 0; k < 256; k++) {
            const float4 a = trow[k], v = wr[k];
            acc += a.x*v.x + a.y*v.y + a.z*v.z + a.w*v.w;
        }
        const float resid = y[b*144 + j] - w[((size_t)b*16 + 15)*144 + j];
        const float d = acc - resid;
        local += d*d;
    }
    __shared__ float red[256];
    red[tid] = local; __syncthreads();
    for (int s = 128; s > 0; s >>= 1) {
        if (tid < s) red[tid] += red[tid+s];
        __syncthreads();
    }
    if (tid == 0) out[0] = red[0] / 1152.f;
}

// ---------------------------------------------------------------------------
extern "C" void kernel_launch(void* const* d_in, const int* in_sizes, int n_in,
                              void* d_out, int out_size) {
    (void)in_sizes; (void)n_in; (void)out_size;
    const float* x      = (const float*)d_in[0];
    const float* w      = (const float*)d_in[1];
    const float* y      = (const float*)d_in[2];
    const float* W_nail = (const float*)d_in[3];
    const float* b_nail = (const float*)d_in[4];
    const float* W_cond = (const float*)d_in[5];
    const float* b_cond = (const float*)d_in[6];
    const float* Wqkv   = (const float*)d_in[7];
    const float* bqkv   = (const float*)d_in[8];
    const float* Wo     = (const float*)d_in[9];
    const float* bo     = (const float*)d_in[10];
    const float* ln1_g  = (const float*)d_in[11];
    const float* ln1_b  = (const float*)d_in[12];
    const float* ln2_g  = (const float*)d_in[13];
    const float* ln2_b  = (const float*)d_in[14];
    const float* W1     = (const float*)d_in[15];
    const float* b1     = (const float*)d_in[16];
    const float* W2     = (const float*)d_in[17];
    const float* b2     = (const float*)d_in[18];
    const float* W_ham  = (const float*)d_in[19];
    const float* b_ham  = (const float*)d_in[20];

    float *tgt, *big, *mid;
    cudaGetSymbolAddress((void**)&tgt, g_tgt);
    cudaGetSymbolAddress((void**)&big, g_big);
    cudaGetSymbolAddress((void**)&mid, g_mid);

    prep_kernel<<<MTOT, 256>>>(x, w, W_nail, b_nail, W_cond, b_cond, tgt);

    for (int i = 0; i < NLAYERS; i++) {
        const float* Wqkv_i = Wqkv + (size_t)i*3*DD*DD;
        const float* bqkv_i = bqkv + (size_t)i*3*DD;
        const float* Wo_i   = Wo   + (size_t)i*DD*DD;
        const float* bo_i   = bo   + (size_t)i*DD;
        const float* W1_i   = W1   + (size_t)i*FFD*DD;
        const float* b1_i   = b1   + (size_t)i*FFD;
        const float* W2_i   = W2   + (size_t)i*DD*FFD;
        const float* b2_i   = b2   + (size_t)i*DD;

        // qkv = tgt @ Wqkv^T + bqkv   -> big (M x 3072)
        gemm_nt_bias<false><<<dim3(24, 56), 256>>>(tgt, Wqkv_i, bqkv_i, big, MTOT, 3*DD, DD);
        // attention -> mid (M x 1024)
        flash_attn_kernel<<<dim3(7, BB*NH), 128>>>(big, mid);
        // o-proj -> big (M x 1024)
        gemm_nt_bias<false><<<dim3(8, 56), 256>>>(mid, Wo_i, bo_i, big, MTOT, DD, DD);
        // tgt = LN(tgt + o)
        add_ln_kernel<<<MTOT, 256>>>(tgt, big, ln1_g + (size_t)i*DD, ln1_b + (size_t)i*DD);
        // ff1 + gelu -> big (M x 4096)
        gemm_nt_bias<true><<<dim3(32, 56), 256>>>(tgt, W1_i, b1_i, big, MTOT, FFD, DD);
        // ff2 -> mid (M x 1024)
        gemm_nt_bias<false><<<dim3(8, 56), 256>>>(big, W2_i, b2_i, mid, MTOT, DD, FFD);
        // tgt = LN(tgt + ff)
        add_ln_kernel<<<MTOT, 256>>>(tgt, mid, ln2_g + (size_t)i*DD, ln2_b + (size_t)i*DD);
    }

    loss_kernel<<<1, 256>>>(tgt, W_ham, b_ham, y, w, (float*)d_out);
}

// round 8
// speedup vs baseline: 4.2987x; 4.2987x over previous
#include <cuda_runtime.h>
#include <cuda_fp16.h>
#include <math.h>
#include <stdint.h>

// Problem constants
#define BB 8
#define SS 896
#define LX 512
#define DD 1024
#define MTOT (BB*SS)    // 7168
#define NH 16
#define FFD 4096
#define NLAYERS 4

// fp16 weight buffer offsets (elements)
#define W_QKV_OFF 0
#define W_O_OFF   12582912
#define W_F1_OFF  16777216
#define W_F2_OFF  33554432
#define W_TOT     50331648

// Scratch (__device__ globals; allocation-free)
__device__ float  g_tgt[MTOT*DD];      // fp32 residual stream
__device__ float  g_big[MTOT*3*DD];    // qkv fp32
__device__ float  g_mid[MTOT*DD];      // o-proj / ff2 fp32 outputs
__device__ __half g_xh[MTOT*DD];       // fp16 activation (GEMM A operand)
__device__ __half g_gh[MTOT*FFD];      // fp16 gelu intermediate
__device__ __half g_wh[W_TOT];         // fp16 weights

__device__ __forceinline__ uint32_t smem_u32(const void* p) {
    uint32_t a;
    asm("{ .reg .u64 t; cvta.to.shared.u64 t, %1; cvt.u32.u64 %0, t; }" : "=r"(a) : "l"(p));
    return a;
}

// ---------------------------------------------------------------------------
// Weight convert fp32 -> fp16
// ---------------------------------------------------------------------------
__global__ void cvt_kernel(const float* __restrict__ s, __half* __restrict__ d, int n4) {
    int i = blockIdx.x * blockDim.x + threadIdx.x;
    if (i >= n4) return;
    float4 v = ((const float4*)s)[i];
    __half2 h0 = __floats2half2_rn(v.x, v.y);
    __half2 h1 = __floats2half2_rn(v.z, v.w);
    uint2 u;
    u.x = *(uint32_t*)&h0;
    u.y = *(uint32_t*)&h1;
    ((uint2*)d)[i] = u;
}

// ---------------------------------------------------------------------------
// fp16 HMMA GEMM: C[M,N] = A[M,K] @ W[N,K]^T + bias
// mma.sync m16n8k16, tile 128x128, BK=64, cp.async double buffer, 256 thr.
// MODE 0: fp32 out (Cf).  MODE 1: exact GELU then fp16 out (Ch).
// ---------------------------------------------------------------------------
#define GEMM_SMEM 65536

template<int MODE>
__global__ __launch_bounds__(256) void gemm_f16(
        const __half* __restrict__ A, const __half* __restrict__ B,
        const float* __restrict__ bias, float* __restrict__ Cf,
        __half* __restrict__ Ch, int M, int N, int K) {
    extern __shared__ char smem[];
    const uint32_t sb = smem_u32(smem);
    const int tid = threadIdx.x, lane = tid & 31, wid = tid >> 5;
    const int wm = wid & 1, wn = wid >> 1;          // 2 x 4 warp grid
    const int m0 = blockIdx.y * 128, n0 = blockIdx.x * 128;

    float acc[4][4][4];
    #pragma unroll
    for (int a = 0; a < 4; a++)
        #pragma unroll
        for (int b = 0; b < 4; b++)
            #pragma unroll
            for (int cc = 0; cc < 4; cc++) acc[a][b][cc] = 0.f;

    auto load_chunk = [&](int c, int s) {
        const int k0 = c << 6;
        #pragma unroll
        for (int i = 0; i < 4; i++) {
            int u = tid + (i << 8);
            int row = u >> 3, cc = u & 7;
            uint32_t dA = sb + s * 16384 + row * 128 + ((cc ^ (row & 7)) << 4);
            const void* gA = A + (size_t)(m0 + row) * K + k0 + cc * 8;
            asm volatile("cp.async.cg.shared.global [%0], [%1], 16;" :: "r"(dA), "l"(gA));
        }
        #pragma unroll
        for (int i = 0; i < 4; i++) {
            int u = tid + (i << 8);
            int row = u >> 3, cc = u & 7;
            uint32_t dB = sb + 32768 + s * 16384 + row * 128 + ((cc ^ (row & 7)) << 4);
            const void* gB = B + (size_t)(n0 + row) * K + k0 + cc * 8;
            asm volatile("cp.async.cg.shared.global [%0], [%1], 16;" :: "r"(dB), "l"(gB));
        }
        asm volatile("cp.async.commit_group;" ::: "memory");
    };

    const int NC = K >> 6;
    load_chunk(0, 0);
    for (int c = 0; c < NC; c++) {
        const int s = c & 1;
        if (c + 1 < NC) {
            load_chunk(c + 1, s ^ 1);
            asm volatile("cp.async.wait_group 1;" ::: "memory");
        } else {
            asm volatile("cp.async.wait_group 0;" ::: "memory");
        }
        __syncthreads();

        const uint32_t arow = sb + s * 16384 + (wm * 64 + (lane & 15)) * 128;
        const uint32_t brow = sb + 32768 + s * 16384
                            + (wn * 32 + ((lane >> 4) << 3) + (lane & 7)) * 128;
        const int ac = (lane >> 4), bc = ((lane >> 3) & 1), lx = lane & 7;

        #pragma unroll
        for (int ks = 0; ks < 4; ks++) {
            uint32_t a[4][4], b[4][2];
            const uint32_t axor = (uint32_t)(((2 * ks + ac) ^ lx) << 4);
            const uint32_t bxor = (uint32_t)(((2 * ks + bc) ^ lx) << 4);
            #pragma unroll
            for (int mt = 0; mt < 4; mt++) {
                asm volatile("ldmatrix.sync.aligned.m8n8.x4.shared.b16 {%0,%1,%2,%3}, [%4];"
                    : "=r"(a[mt][0]), "=r"(a[mt][1]), "=r"(a[mt][2]), "=r"(a[mt][3])
                    : "r"(arow + mt * 2048 + axor));
            }
            #pragma unroll
            for (int p = 0; p < 2; p++) {
                uint32_t r0, r1, r2, r3;
                asm volatile("ldmatrix.sync.aligned.m8n8.x4.shared.b16 {%0,%1,%2,%3}, [%4];"
                    : "=r"(r0), "=r"(r1), "=r"(r2), "=r"(r3)
                    : "r"(brow + p * 2048 + bxor));
                b[2*p][0] = r0; b[2*p][1] = r1; b[2*p+1][0] = r2; b[2*p+1][1] = r3;
            }
            #pragma unroll
            for (int mt = 0; mt < 4; mt++)
                #pragma unroll
                for (int nt = 0; nt < 4; nt++)
                    asm volatile(
                        "mma.sync.aligned.m16n8k16.row.col.f32.f16.f16.f32 "
                        "{%0,%1,%2,%3}, {%4,%5,%6,%7}, {%8,%9}, {%0,%1,%2,%3};"
                        : "+f"(acc[mt][nt][0]), "+f"(acc[mt][nt][1]),
                          "+f"(acc[mt][nt][2]), "+f"(acc[mt][nt][3])
                        : "r"(a[mt][0]), "r"(a[mt][1]), "r"(a[mt][2]), "r"(a[mt][3]),
                          "r"(b[nt][0]), "r"(b[nt][1]));
        }
        __syncthreads();
    }

    // Epilogue (register -> global, fused bias/GELU)
    #pragma unroll
    for (int mt = 0; mt < 4; mt++) {
        const int m = m0 + wm * 64 + mt * 16 + (lane >> 2);
        #pragma unroll
        for (int nt = 0; nt < 4; nt++) {
            const int n = n0 + wn * 32 + nt * 8 + (lane & 3) * 2;
            const float b0 = bias[n], b1 = bias[n + 1];
            float v0 = acc[mt][nt][0] + b0, v1 = acc[mt][nt][1] + b1;
            float v2 = acc[mt][nt][2] + b0, v3 = acc[mt][nt][3] + b1;
            if (MODE == 1) {
                v0 = 0.5f * v0 * (1.0f + erff(v0 * 0.70710678118654752f));
                v1 = 0.5f * v1 * (1.0f + erff(v1 * 0.70710678118654752f));
                v2 = 0.5f * v2 * (1.0f + erff(v2 * 0.70710678118654752f));
                v3 = 0.5f * v3 * (1.0f + erff(v3 * 0.70710678118654752f));
                *(__half2*)(Ch + (size_t)m * N + n)       = __floats2half2_rn(v0, v1);
                *(__half2*)(Ch + (size_t)(m + 8) * N + n) = __floats2half2_rn(v2, v3);
            } else {
                float2 f01, f23;
                f01.x = v0; f01.y = v1; f23.x = v2; f23.y = v3;
                *(float2*)(Cf + (size_t)m * N + n)       = f01;
                *(float2*)(Cf + (size_t)(m + 8) * N + n) = f23;
            }
        }
    }
}

// ---------------------------------------------------------------------------
// Prep: build tgt (fp32) + fp16 copy
// ---------------------------------------------------------------------------
__global__ void prep_kernel(const float* __restrict__ x, const float* __restrict__ w,
                            const float* __restrict__ Wn, const float* __restrict__ bn,
                            const float* __restrict__ Wc, const float* __restrict__ bc,
                            float* __restrict__ tgt, __half* __restrict__ xh) {
    const int row = blockIdx.x;
    const int b = row / SS, s = row % SS;
    const int tid = threadIdx.x;
    __shared__ float f[64];
    __shared__ float sh_t;
    const float rs = 0.9999500037496877f;        // 1/sqrt(1+1e-4)
    const float cdiv = -0.0067458547646309937f;  // -log(1000)/1024

    if (s < LX) {
        if (tid < 64) {
            float v = x[((size_t)b*LX + s)*64 + tid];
            if (isnan(v)) v = 0.f;
            if (tid == 0) sh_t = v;
            v *= rs;
            v = fminf(5.f, fmaxf(-5.f, v));
            f[tid] = v;
        }
        __syncthreads();
        const float t = sh_t;
        #pragma unroll
        for (int it = 0; it < 4; it++) {
            const int d = tid + it*256;
            float acc = bn[d];
            const float* wr = Wn + (size_t)d*63;
            #pragma unroll 7
            for (int k = 0; k < 63; k++) acc += f[k+1]*wr[k];
            const int i = d >> 1;
            const float div = expf((float)i * cdiv);
            const float ang = t * div;
            acc += (d & 1) ? cosf(ang) : sinf(ang);
            tgt[(size_t)row*DD + d] = acc;
            xh[(size_t)row*DD + d] = __float2half(acc);
        }
    } else {
        const int j = s - LX;
        if (tid < 6) {
            float v = w[((size_t)b*384 + j)*6 + tid];
            if (isnan(v)) v = 0.f;
            v *= rs;
            v = fminf(5.f, fmaxf(-5.f, v));
            f[tid] = v;
        }
        __syncthreads();
        const float pos = (float)s;
        #pragma unroll
        for (int it = 0; it < 4; it++) {
            const int d = tid + it*256;
            float acc = bc[d];
            const float* wr = Wc + (size_t)d*6;
            #pragma unroll
            for (int k = 0; k < 6; k++) acc += f[k]*wr[k];
            const int i = d >> 1;
            const float div = expf((float)i * cdiv);
            const float ang = pos * div;
            acc += (d & 1) ? cosf(ang) : sinf(ang);
            tgt[(size_t)row*DD + d] = acc;
            xh[(size_t)row*DD + d] = __float2half(acc);
        }
    }
}

// ---------------------------------------------------------------------------
// Flash attention, fp32 math (__expf), fp16 output (o-proj A operand).
// qkv layout: [B*S, 3072] = [q | k | v]. cols<512 always visible; else causal.
// ---------------------------------------------------------------------------
__global__ __launch_bounds__(128) void flash_attn_kernel(
        const float* __restrict__ qkv, __half* __restrict__ xh) {
    const int q0 = blockIdx.x * 128;
    const int bh = blockIdx.y;
    const int b = bh >> 4, h = bh & 15;
    const int tid = threadIdx.x;
    const int qrow = q0 + tid;
    const float* base = qkv + (size_t)b * SS * 3072;
    __shared__ __align__(16) float Ks[32*64];
    __shared__ __align__(16) float Vs[32*64];
    __shared__ __align__(16) float Ps[32*128];
    float q[64], acc[64];
    {
        const float* qp = base + (size_t)qrow*3072 + h*64;
        #pragma unroll
        for (int i = 0; i < 16; i++) {
            float4 vv = *(const float4*)(qp + i*4);
            q[i*4+0]=vv.x; q[i*4+1]=vv.y; q[i*4+2]=vv.z; q[i*4+3]=vv.w;
        }
    }
    #pragma unroll
    for (int d = 0; d < 64; d++) acc[d] = 0.f;
    float mval = -1e30f, lsum = 0.f;
    int kt_end = (q0 + 127) / 32 + 1;
    if (kt_end < 16) kt_end = 16;
    for (int kt = 0; kt < kt_end; kt++) {
        const int c0 = kt * 32;
        __syncthreads();
        #pragma unroll
        for (int i = 0; i < 4; i++) {
            const int slot = i*128 + tid;
            const int row = slot >> 4, col4 = slot & 15;
            const float* kp = base + (size_t)(c0+row)*3072 + 1024 + h*64 + col4*4;
            ((float4*)Ks)[slot] = *(const float4*)kp;
            ((float4*)Vs)[slot] = *(const float4*)(kp + 1024);
        }
        __syncthreads();
        const int jlim = (c0 + 32 <= LX) ? 32 : (qrow - c0 + 1);
        float tmax = -1e30f;
        #pragma unroll 2
        for (int j = 0; j < 32; j++) {
            float s = 0.f;
            const float4* kr = (const float4*)(Ks + j*64);
            #pragma unroll
            for (int d4 = 0; d4 < 16; d4++) {
                const float4 kk = kr[d4];
                s += q[d4*4+0]*kk.x + q[d4*4+1]*kk.y + q[d4*4+2]*kk.z + q[d4*4+3]*kk.w;
            }
            s *= 0.125f;
            if (j >= jlim) s = -1e30f;
            Ps[j*128 + tid] = s;
            tmax = fmaxf(tmax, s);
        }
        if (tmax > -1e29f) {
            const float mnew = fmaxf(mval, tmax);
            const float alpha = __expf(mval - mnew);
            lsum *= alpha;
            #pragma unroll
            for (int d = 0; d < 64; d++) acc[d] *= alpha;
            #pragma unroll 2
            for (int j = 0; j < 32; j++) {
                const float e = __expf(Ps[j*128 + tid] - mnew);
                lsum += e;
                const float4* vr = (const float4*)(Vs + j*64);
                #pragma unroll
                for (int d4 = 0; d4 < 16; d4++) {
                    const float4 vv = vr[d4];
                    acc[d4*4+0] += e*vv.x; acc[d4*4+1] += e*vv.y;
                    acc[d4*4+2] += e*vv.z; acc[d4*4+3] += e*vv.w;
                }
            }
            mval = mnew;
        }
    }
    const float inv = 1.f / lsum;
    const size_t oo = (size_t)(b*SS + qrow)*DD + h*64;
    #pragma unroll
    for (int i = 0; i < 16; i++) {
        *(__half2*)(xh + oo + i*4)     = __floats2half2_rn(acc[i*4+0]*inv, acc[i*4+1]*inv);
        *(__half2*)(xh + oo + i*4 + 2) = __floats2half2_rn(acc[i*4+2]*inv, acc[i*4+3]*inv);
    }
}

// ---------------------------------------------------------------------------
// x = LayerNorm(x + r)*g + b (in-place, fp32) + fp16 copy
// ---------------------------------------------------------------------------
__global__ __launch_bounds__(256) void add_ln_kernel(
        float* __restrict__ x, const float* __restrict__ r,
        const float* __restrict__ g, const float* __restrict__ bt,
        __half* __restrict__ xh) {
    const int row = blockIdx.x;
    const int tid = threadIdx.x;
    const size_t off = (size_t)row*DD + tid*4;
    float4 xv = *(float4*)(x + off);
    const float4 rv = *(const float4*)(r + off);
    xv.x += rv.x; xv.y += rv.y; xv.z += rv.z; xv.w += rv.w;
    float s  = xv.x + xv.y + xv.z + xv.w;
    float s2 = xv.x*xv.x + xv.y*xv.y + xv.z*xv.z + xv.w*xv.w;
    __shared__ float sh[16];
    #pragma unroll
    for (int o = 16; o; o >>= 1) {
        s  += __shfl_xor_sync(0xffffffffu, s,  o);
        s2 += __shfl_xor_sync(0xffffffffu, s2, o);
    }
    const int warp = tid >> 5, lane = tid & 31;
    if (lane == 0) { sh[warp] = s; sh[warp+8] = s2; }
    __syncthreads();
    if (tid < 32) {
        float a  = (lane < 8) ? sh[lane]   : 0.f;
        float a2 = (lane < 8) ? sh[lane+8] : 0.f;
        #pragma unroll
        for (int o = 4; o; o >>= 1) {
            a  += __shfl_xor_sync(0xffffffffu, a,  o);
            a2 += __shfl_xor_sync(0xffffffffu, a2, o);
        }
        if (lane == 0) { sh[0] = a; sh[1] = a2; }
    }
    __syncthreads();
    const float mean = sh[0] * (1.f/1024.f);
    const float var  = sh[1] * (1.f/1024.f) - mean*mean;
    const float rstd = 1.f / sqrtf(var + 1e-5f);
    const float4 gv = *(const float4*)(g  + tid*4);
    const float4 bv = *(const float4*)(bt + tid*4);
    float4 o;
    o.x = (xv.x - mean)*rstd*gv.x + bv.x;
    o.y = (xv.y - mean)*rstd*gv.y + bv.y;
    o.z = (xv.z - mean)*rstd*gv.z + bv.z;
    o.w = (xv.w - mean)*rstd*gv.w + bv.w;
    *(float4*)(x + off) = o;
    *(__half2*)(xh + off)     = __floats2half2_rn(o.x, o.y);
    *(__half2*)(xh + off + 2) = __floats2half2_rn(o.z, o.w);
}

// ---------------------------------------------------------------------------
// loss = mean((tgt[:,-1] @ W_ham^T + b_ham - (y - w_last))^2), fp32
// ---------------------------------------------------------------------------
__global__ void loss_kernel(const float* __restrict__ tgt, const float* __restrict__ Wh,
                            const float* __restrict__ bh, const float* __restrict__ y,
                            const float* __restrict__ w, float* __restrict__ out) {
    const int tid = threadIdx.x;
    float local = 0.f;
    for (int e = tid; e < 8*144; e += 256) {
        const int b = e / 144, j = e % 144;
        const float4* trow = (const float4*)(tgt + ((size_t)b*SS + SS-1)*DD);
        const float4* wr   = (const float4*)(Wh + (size_t)j*DD);
        float acc = bh[j];
        for (int k = 0; k < 256; k++) {
            const float4 a = trow[k], v = wr[k];
            acc += a.x*v.x + a.y*v.y + a.z*v.z + a.w*v.w;
        }
        const float resid = y[b*144 + j] - w[((size_t)b*16 + 15)*144 + j];
        const float d = acc - resid;
        local += d*d;
    }
    __shared__ float red[256];
    red[tid] = local; __syncthreads();
    for (int s = 128; s > 0; s >>= 1) {
        if (tid < s) red[tid] += red[tid+s];
        __syncthreads();
    }
    if (tid == 0) out[0] = red[0] / 1152.f;
}

// ---------------------------------------------------------------------------
extern "C" void kernel_launch(void* const* d_in, const int* in_sizes, int n_in,
                              void* d_out, int out_size) {
    (void)in_sizes; (void)n_in; (void)out_size;
    const float* x      = (const float*)d_in[0];
    const float* w      = (const float*)d_in[1];
    const float* y      = (const float*)d_in[2];
    const float* W_nail = (const float*)d_in[3];
    const float* b_nail = (const float*)d_in[4];
    const float* W_cond = (const float*)d_in[5];
    const float* b_cond = (const float*)d_in[6];
    const float* Wqkv   = (const float*)d_in[7];
    const float* bqkv   = (const float*)d_in[8];
    const float* Wo     = (const float*)d_in[9];
    const float* bo     = (const float*)d_in[10];
    const float* ln1_g  = (const float*)d_in[11];
    const float* ln1_b  = (const float*)d_in[12];
    const float* ln2_g  = (const float*)d_in[13];
    const float* ln2_b  = (const float*)d_in[14];
    const float* W1     = (const float*)d_in[15];
    const float* b1     = (const float*)d_in[16];
    const float* W2     = (const float*)d_in[17];
    const float* b2     = (const float*)d_in[18];
    const float* W_ham  = (const float*)d_in[19];
    const float* b_ham  = (const float*)d_in[20];

    float *tgt, *big, *mid;
    __half *xh, *gh, *wh;
    cudaGetSymbolAddress((void**)&tgt, g_tgt);
    cudaGetSymbolAddress((void**)&big, g_big);
    cudaGetSymbolAddress((void**)&mid, g_mid);
    cudaGetSymbolAddress((void**)&xh,  g_xh);
    cudaGetSymbolAddress((void**)&gh,  g_gh);
    cudaGetSymbolAddress((void**)&wh,  g_wh);

    cudaFuncSetAttribute(gemm_f16<0>, cudaFuncAttributeMaxDynamicSharedMemorySize, GEMM_SMEM);
    cudaFuncSetAttribute(gemm_f16<1>, cudaFuncAttributeMaxDynamicSharedMemorySize, GEMM_SMEM);

    // Weight converts (fp32 -> fp16), once per launch
    {
        int n4;
        n4 = (4*3*DD*DD)/4;
        cvt_kernel<<<(n4+255)/256, 256>>>(Wqkv, wh + W_QKV_OFF, n4);
        n4 = (4*DD*DD)/4;
        cvt_kernel<<<(n4+255)/256, 256>>>(Wo,   wh + W_O_OFF,  n4);
        n4 = (4*FFD*DD)/4;
        cvt_kernel<<<(n4+255)/256, 256>>>(W1,   wh + W_F1_OFF, n4);
        n4 = (4*DD*FFD)/4;
        cvt_kernel<<<(n4+255)/256, 256>>>(W2,   wh + W_F2_OFF, n4);
    }

    prep_kernel<<<MTOT, 256>>>(x, w, W_nail, b_nail, W_cond, b_cond, tgt, xh);

    for (int i = 0; i < NLAYERS; i++) {
        const __half* wq = wh + W_QKV_OFF + (size_t)i*3*DD*DD;
        const __half* wo = wh + W_O_OFF   + (size_t)i*DD*DD;
        const __half* w1 = wh + W_F1_OFF  + (size_t)i*FFD*DD;
        const __half* w2 = wh + W_F2_OFF  + (size_t)i*DD*FFD;
        const float* bqkv_i = bqkv + (size_t)i*3*DD;
        const float* bo_i   = bo   + (size_t)i*DD;
        const float* b1_i   = b1   + (size_t)i*FFD;
        const float* b2_i   = b2   + (size_t)i*DD;

        // qkv = x @ Wqkv^T + b  -> big (fp32)
        gemm_f16<0><<<dim3(24, 56), 256, GEMM_SMEM>>>(xh, wq, bqkv_i, big, nullptr, MTOT, 3*DD, DD);
        // attention -> xh (fp16, o-proj A operand)
        flash_attn_kernel<<<dim3(7, BB*NH), 128>>>(big, xh);
        // o-proj -> mid (fp32)
        gemm_f16<0><<<dim3(8, 56), 256, GEMM_SMEM>>>(xh, wo, bo_i, mid, nullptr, MTOT, DD, DD);
        // tgt = LN(tgt + o); writes xh
        add_ln_kernel<<<MTOT, 256>>>(tgt, mid, ln1_g + (size_t)i*DD, ln1_b + (size_t)i*DD, xh);
        // ff1 + gelu -> gh (fp16)
        gemm_f16<1><<<dim3(32, 56), 256, GEMM_SMEM>>>(xh, w1, b1_i, nullptr, gh, MTOT, FFD, DD);
        // ff2 -> mid (fp32)
        gemm_f16<0><<<dim3(8, 56), 256, GEMM_SMEM>>>(gh, w2, b2_i, mid, nullptr, MTOT, DD, FFD);
        // tgt = LN(tgt + ff); writes xh
        add_ln_kernel<<<MTOT, 256>>>(tgt, mid, ln2_g + (size_t)i*DD, ln2_b + (size_t)i*DD, xh);
    }

    loss_kernel<<<1, 256>>>(tgt, W_ham, b_ham, y, w, (float*)d_out);
}

// round 11
// speedup vs baseline: 4.3589x; 1.0140x over previous
#include <cuda_runtime.h>
#include <cuda_fp16.h>
#include <math.h>
#include <stdint.h>

// Problem constants
#define BB 8
#define SS 896
#define LX 512
#define DD 1024
#define MTOT (BB*SS)    // 7168
#define NH 16
#define FFD 4096
#define NLAYERS 4

// fp16 weight buffer offsets (elements)
#define W_QKV_OFF 0
#define W_O_OFF   12582912
#define W_F1_OFF  16777216
#define W_F2_OFF  33554432
#define W_TOT     50331648

// Scratch (__device__ globals; allocation-free)
__device__ float  g_tgt[MTOT*DD];      // fp32 residual stream
__device__ float  g_mid[MTOT*DD];      // o-proj / ff2 fp32 outputs
__device__ __half g_qh[MTOT*3*DD];     // qkv fp16
__device__ __half g_xh[MTOT*DD];       // fp16 activation (GEMM A operand)
__device__ __half g_gh[MTOT*FFD];      // fp16 gelu intermediate
__device__ __half g_wh[W_TOT];         // fp16 weights
__device__ float  g_div[512];          // sinusoidal div table
__device__ float  g_pet[384*DD];       // exact PE for pos 512..895

__device__ __forceinline__ uint32_t smem_u32(const void* p) {
    uint32_t a;
    asm("{ .reg .u64 t; cvta.to.shared.u64 t, %1; cvt.u32.u64 %0, t; }" : "=r"(a) : "l"(p));
    return a;
}
__device__ __forceinline__ void h8f(uint4 p, float* dst) {
    const __half2* hp = (const __half2*)&p;
    #pragma unroll
    for (int t = 0; t < 4; t++) {
        float2 f = __half22float2(hp[t]);
        dst[2*t] = f.x; dst[2*t+1] = f.y;
    }
}

// ---------------------------------------------------------------------------
// Fused weight convert fp32 -> fp16 (all four weight tensors, one launch)
// ---------------------------------------------------------------------------
#define N4_QKV 3145728
#define N4_O   1048576
#define N4_F1  4194304
#define N4_F2  4194304
#define N4_TOT (N4_QKV+N4_O+N4_F1+N4_F2)

__global__ void cvt_all_kernel(const float* __restrict__ wq, const float* __restrict__ wo,
                               const float* __restrict__ w1, const float* __restrict__ w2,
                               __half* __restrict__ d) {
    int i = blockIdx.x * blockDim.x + threadIdx.x;
    if (i >= N4_TOT) return;
    const float* s; size_t off;
    if (i < N4_QKV)                 { s = wq; off = i;                       }
    else if (i < N4_QKV+N4_O)       { s = wo; off = i - N4_QKV;             }
    else if (i < N4_QKV+N4_O+N4_F1) { s = w1; off = i - (N4_QKV+N4_O);      }
    else                            { s = w2; off = i - (N4_QKV+N4_O+N4_F1);}
    float4 v = ((const float4*)s)[off];
    __half2 h0 = __floats2half2_rn(v.x, v.y);
    __half2 h1 = __floats2half2_rn(v.z, v.w);
    uint2 u;
    u.x = *(uint32_t*)&h0;
    u.y = *(uint32_t*)&h1;
    ((uint2*)d)[i] = u;
}

// ---------------------------------------------------------------------------
// Tables: div[i] = exp(i * -log(1000)/1024); pe table for pos 512..895 (exact)
// ---------------------------------------------------------------------------
__global__ void div_kernel(float* __restrict__ dv) {
    int i = threadIdx.x;   // 512
    dv[i] = expf((float)i * -0.0067458547646309937f);
}
__global__ void pe_kernel(const float* __restrict__ dv, float* __restrict__ pet) {
    const int pos = 512 + blockIdx.x;     // 512..895
    const int tid = threadIdx.x;          // 256
    #pragma unroll
    for (int it = 0; it < 4; it++) {
        const int d = tid + it*256;
        const float ang = (float)pos * dv[d >> 1];
        pet[blockIdx.x*DD + d] = (d & 1) ? cosf(ang) : sinf(ang);
    }
}

// ---------------------------------------------------------------------------
// fp16 HMMA GEMM: C[M,N] = A[M,K] @ W[N,K]^T + bias
// mma.sync m16n8k16, tile 128x128, BK=64, 3-stage cp.async, 256 thr, 2 CTA/SM.
// MODE 0: fp32 out. MODE 1: exact GELU, fp16 out. MODE 2: fp16 out.
// ---------------------------------------------------------------------------
#define GEMM_SMEM (3*32768)

template<int MODE>
__global__ __launch_bounds__(256, 2) void gemm_f16(
        const __half* __restrict__ A, const __half* __restrict__ B,
        const float* __restrict__ bias, float* __restrict__ Cf,
        __half* __restrict__ Ch, int M, int N, int K) {
    extern __shared__ char smem[];
    const uint32_t sb = smem_u32(smem);
    const int tid = threadIdx.x, lane = tid & 31, wid = tid >> 5;
    const int wm = wid & 1, wn = wid >> 1;          // 2 x 4 warp grid
    const int m0 = blockIdx.y * 128, n0 = blockIdx.x * 128;

    float acc[4][4][4];
    #pragma unroll
    for (int a = 0; a < 4; a++)
        #pragma unroll
        for (int b = 0; b < 4; b++)
            #pragma unroll
            for (int cc = 0; cc < 4; cc++) acc[a][b][cc] = 0.f;

    auto load_chunk = [&](int c, int s) {
        const int k0 = c << 6;
        const uint32_t stg = sb + s * 32768;
        #pragma unroll
        for (int i = 0; i < 4; i++) {
            int u = tid + (i << 8);
            int row = u >> 3, cc = u & 7;
            uint32_t dA = stg + row * 128 + ((cc ^ (row & 7)) << 4);
            const void* gA = A + (size_t)(m0 + row) * K + k0 + cc * 8;
            asm volatile("cp.async.cg.shared.global [%0], [%1], 16;" :: "r"(dA), "l"(gA));
        }
        #pragma unroll
        for (int i = 0; i < 4; i++) {
            int u = tid + (i << 8);
            int row = u >> 3, cc = u & 7;
            uint32_t dB = stg + 16384 + row * 128 + ((cc ^ (row & 7)) << 4);
            const void* gB = B + (size_t)(n0 + row) * K + k0 + cc * 8;
            asm volatile("cp.async.cg.shared.global [%0], [%1], 16;" :: "r"(dB), "l"(gB));
        }
        asm volatile("cp.async.commit_group;" ::: "memory");
    };

    const int NC = K >> 6;
    load_chunk(0, 0);
    load_chunk(1, 1);
    int s3 = 0;
    for (int c = 0; c < NC; c++) {
        if (c + 1 < NC) asm volatile("cp.async.wait_group 1;" ::: "memory");
        else            asm volatile("cp.async.wait_group 0;" ::: "memory");
        __syncthreads();
        if (c + 2 < NC) {
            int sn = s3 + 2; if (sn >= 3) sn -= 3;
            load_chunk(c + 2, sn);
        }

        const uint32_t stg = sb + s3 * 32768;
        const uint32_t arow = stg + (wm * 64 + (lane & 15)) * 128;
        const uint32_t brow = stg + 16384
                            + (wn * 32 + ((lane >> 4) << 3) + (lane & 7)) * 128;
        const int ac = (lane >> 4), bc = ((lane >> 3) & 1), lx = lane & 7;

        #pragma unroll
        for (int ks = 0; ks < 4; ks++) {
            uint32_t a[4][4], b[4][2];
            const uint32_t axor = (uint32_t)(((2 * ks + ac) ^ lx) << 4);
            const uint32_t bxor = (uint32_t)(((2 * ks + bc) ^ lx) << 4);
            #pragma unroll
            for (int mt = 0; mt < 4; mt++) {
                asm volatile("ldmatrix.sync.aligned.m8n8.x4.shared.b16 {%0,%1,%2,%3}, [%4];"
                    : "=r"(a[mt][0]), "=r"(a[mt][1]), "=r"(a[mt][2]), "=r"(a[mt][3])
                    : "r"(arow + mt * 2048 + axor));
            }
            #pragma unroll
            for (int p = 0; p < 2; p++) {
                uint32_t r0, r1, r2, r3;
                asm volatile("ldmatrix.sync.aligned.m8n8.x4.shared.b16 {%0,%1,%2,%3}, [%4];"
                    : "=r"(r0), "=r"(r1), "=r"(r2), "=r"(r3)
                    : "r"(brow + p * 2048 + bxor));
                b[2*p][0] = r0; b[2*p][1] = r1; b[2*p+1][0] = r2; b[2*p+1][1] = r3;
            }
            #pragma unroll
            for (int mt = 0; mt < 4; mt++)
                #pragma unroll
                for (int nt = 0; nt < 4; nt++)
                    asm volatile(
                        "mma.sync.aligned.m16n8k16.row.col.f32.f16.f16.f32 "
                        "{%0,%1,%2,%3}, {%4,%5,%6,%7}, {%8,%9}, {%0,%1,%2,%3};"
                        : "+f"(acc[mt][nt][0]), "+f"(acc[mt][nt][1]),
                          "+f"(acc[mt][nt][2]), "+f"(acc[mt][nt][3])
                        : "r"(a[mt][0]), "r"(a[mt][1]), "r"(a[mt][2]), "r"(a[mt][3]),
                          "r"(b[nt][0]), "r"(b[nt][1]));
        }
        __syncthreads();
        s3++; if (s3 == 3) s3 = 0;
    }

    // Epilogue (register -> global, fused bias/GELU/fp16)
    #pragma unroll
    for (int mt = 0; mt < 4; mt++) {
        const int m = m0 + wm * 64 + mt * 16 + (lane >> 2);
        #pragma unroll
        for (int nt = 0; nt < 4; nt++) {
            const int n = n0 + wn * 32 + nt * 8 + (lane & 3) * 2;
            const float b0 = bias[n], b1 = bias[n + 1];
            float v0 = acc[mt][nt][0] + b0, v1 = acc[mt][nt][1] + b1;
            float v2 = acc[mt][nt][2] + b0, v3 = acc[mt][nt][3] + b1;
            if (MODE == 1) {
                v0 = 0.5f * v0 * (1.0f + erff(v0 * 0.70710678118654752f));
                v1 = 0.5f * v1 * (1.0f + erff(v1 * 0.70710678118654752f));
                v2 = 0.5f * v2 * (1.0f + erff(v2 * 0.70710678118654752f));
                v3 = 0.5f * v3 * (1.0f + erff(v3 * 0.70710678118654752f));
            }
            if (MODE == 0) {
                float2 f01, f23;
                f01.x = v0; f01.y = v1; f23.x = v2; f23.y = v3;
                *(float2*)(Cf + (size_t)m * N + n)       = f01;
                *(float2*)(Cf + (size_t)(m + 8) * N + n) = f23;
            } else {
                *(__half2*)(Ch + (size_t)m * N + n)       = __floats2half2_rn(v0, v1);
                *(__half2*)(Ch + (size_t)(m + 8) * N + n) = __floats2half2_rn(v2, v3);
            }
        }
    }
}

// ---------------------------------------------------------------------------
// Prep: build tgt (fp32) + fp16 copy, using div/pe tables
// ---------------------------------------------------------------------------
__global__ void prep_kernel(const float* __restrict__ x, const float* __restrict__ w,
                            const float* __restrict__ Wn, const float* __restrict__ bn,
                            const float* __restrict__ Wc, const float* __restrict__ bc,
                            const float* __restrict__ dv, const float* __restrict__ pet,
                            float* __restrict__ tgt, __half* __restrict__ xh) {
    const int row = blockIdx.x;
    const int b = row / SS, s = row % SS;
    const int tid = threadIdx.x;
    __shared__ float f[64];
    __shared__ float sh_t;
    const float rs = 0.9999500037496877f;        // 1/sqrt(1+1e-4)

    if (s < LX) {
        if (tid < 64) {
            float v = x[((size_t)b*LX + s)*64 + tid];
            if (isnan(v)) v = 0.f;
            if (tid == 0) sh_t = v;
            v *= rs;
            v = fminf(5.f, fmaxf(-5.f, v));
            f[tid] = v;
        }
        __syncthreads();
        const float t = sh_t;
        #pragma unroll
        for (int it = 0; it < 4; it++) {
            const int d = tid + it*256;
            float acc = bn[d];
            const float* wr = Wn + (size_t)d*63;
            #pragma unroll 7
            for (int k = 0; k < 63; k++) acc += f[k+1]*wr[k];
            const float ang = t * dv[d >> 1];
            acc += (d & 1) ? __cosf(ang) : __sinf(ang);   // |ang| <= ~5
            tgt[(size_t)row*DD + d] = acc;
            xh[(size_t)row*DD + d] = __float2half(acc);
        }
    } else {
        const int j = s - LX;
        if (tid < 6) {
            float v = w[((size_t)b*384 + j)*6 + tid];
            if (isnan(v)) v = 0.f;
            v *= rs;
            v = fminf(5.f, fmaxf(-5.f, v));
            f[tid] = v;
        }
        __syncthreads();
        #pragma unroll
        for (int it = 0; it < 4; it++) {
            const int d = tid + it*256;
            float acc = bc[d];
            const float* wr = Wc + (size_t)d*6;
            #pragma unroll
            for (int k = 0; k < 6; k++) acc += f[k]*wr[k];
            acc += pet[(size_t)j*DD + d];
            tgt[(size_t)row*DD + d] = acc;
            xh[(size_t)row*DD + d] = __float2half(acc);
        }
    }
}

// ---------------------------------------------------------------------------
// Flash attention: fp16 qkv input (converted to fp32 in smem), fp32 math,
// __expf softmax, fp16 output. cols<512 always visible; else causal.
// ---------------------------------------------------------------------------
__global__ __launch_bounds__(128) void flash_attn_kernel(
        const __half* __restrict__ qkv, __half* __restrict__ xh) {
    const int q0 = blockIdx.x * 128;
    const int bh = blockIdx.y;
    const int b = bh >> 4, h = bh & 15;
    const int tid = threadIdx.x;
    const int qrow = q0 + tid;
    const __half* base = qkv + (size_t)b * SS * 3072;
    __shared__ __align__(16) float Ks[32*64];
    __shared__ __align__(16) float Vs[32*64];
    __shared__ __align__(16) float Ps[32*128];
    float q[64], acc[64];
    {
        const uint4* qp = (const uint4*)(base + (size_t)qrow*3072 + h*64);
        #pragma unroll
        for (int i = 0; i < 8; i++) h8f(qp[i], &q[i*8]);
    }
    #pragma unroll
    for (int d = 0; d < 64; d++) acc[d] = 0.f;
    float mval = -1e30f, lsum = 0.f;
    int kt_end = (q0 + 127) / 32 + 1;
    if (kt_end < 16) kt_end = 16;
    for (int kt = 0; kt < kt_end; kt++) {
        const int c0 = kt * 32;
        __syncthreads();
        #pragma unroll
        for (int i = 0; i < 2; i++) {
            const int slot = i*128 + tid;           // 0..255
            const int row = slot >> 3, col8 = (slot & 7) << 3;
            const __half* kp = base + (size_t)(c0+row)*3072 + 1024 + h*64 + col8;
            float tk[8], tv[8];
            h8f(*(const uint4*)kp, tk);
            h8f(*(const uint4*)(kp + 1024), tv);
            *(float4*)(Ks + row*64 + col8)     = *(float4*)tk;
            *(float4*)(Ks + row*64 + col8 + 4) = *(float4*)(tk+4);
            *(float4*)(Vs + row*64 + col8)     = *(float4*)tv;
            *(float4*)(Vs + row*64 + col8 + 4) = *(float4*)(tv+4);
        }
        __syncthreads();
        const int jlim = (c0 + 32 <= LX) ? 32 : (qrow - c0 + 1);
        float tmax = -1e30f;
        #pragma unroll 2
        for (int j = 0; j < 32; j++) {
            float s = 0.f;
            const float4* kr = (const float4*)(Ks + j*64);
            #pragma unroll
            for (int d4 = 0; d4 < 16; d4++) {
                const float4 kk = kr[d4];
                s += q[d4*4+0]*kk.x + q[d4*4+1]*kk.y + q[d4*4+2]*kk.z + q[d4*4+3]*kk.w;
            }
            s *= 0.125f;
            if (j >= jlim) s = -1e30f;
            Ps[j*128 + tid] = s;
            tmax = fmaxf(tmax, s);
        }
        if (tmax > -1e29f) {
            const float mnew = fmaxf(mval, tmax);
            const float alpha = __expf(mval - mnew);
            lsum *= alpha;
            #pragma unroll
            for (int d = 0; d < 64; d++) acc[d] *= alpha;
            #pragma unroll 2
            for (int j = 0; j < 32; j++) {
                const float e = __expf(Ps[j*128 + tid] - mnew);
                lsum += e;
                const float4* vr = (const float4*)(Vs + j*64);
                #pragma unroll
                for (int d4 = 0; d4 < 16; d4++) {
                    const float4 vv = vr[d4];
                    acc[d4*4+0] += e*vv.x; acc[d4*4+1] += e*vv.y;
                    acc[d4*4+2] += e*vv.z; acc[d4*4+3] += e*vv.w;
                }
            }
            mval = mnew;
        }
    }
    const float inv = 1.f / lsum;
    const size_t oo = (size_t)(b*SS + qrow)*DD + h*64;
    #pragma unroll
    for (int i = 0; i < 16; i++) {
        *(__half2*)(xh + oo + i*4)     = __floats2half2_rn(acc[i*4+0]*inv, acc[i*4+1]*inv);
        *(__half2*)(xh + oo + i*4 + 2) = __floats2half2_rn(acc[i*4+2]*inv, acc[i*4+3]*inv);
    }
}

// ---------------------------------------------------------------------------
// x = LayerNorm(x + r)*g + b (in-place, fp32) + fp16 copy
// ---------------------------------------------------------------------------
__global__ __launch_bounds__(256) void add_ln_kernel(
        float* __restrict__ x, const float* __restrict__ r,
        const float* __restrict__ g, const float* __restrict__ bt,
        __half* __restrict__ xh) {
    const int row = blockIdx.x;
    const int tid = threadIdx.x;
    const size_t off = (size_t)row*DD + tid*4;
    float4 xv = *(float4*)(x + off);
    const float4 rv = *(const float4*)(r + off);
    xv.x += rv.x; xv.y += rv.y; xv.z += rv.z; xv.w += rv.w;
    float s  = xv.x + xv.y + xv.z + xv.w;
    float s2 = xv.x*xv.x + xv.y*xv.y + xv.z*xv.z + xv.w*xv.w;
    __shared__ float sh[16];
    #pragma unroll
    for (int o = 16; o; o >>= 1) {
        s  += __shfl_xor_sync(0xffffffffu, s,  o);
        s2 += __shfl_xor_sync(0xffffffffu, s2, o);
    }
    const int warp = tid >> 5, lane = tid & 31;
    if (lane == 0) { sh[warp] = s; sh[warp+8] = s2; }
    __syncthreads();
    if (tid < 32) {
        float a  = (lane < 8) ? sh[lane]   : 0.f;
        float a2 = (lane < 8) ? sh[lane+8] : 0.f;
        #pragma unroll
        for (int o = 4; o; o >>= 1) {
            a  += __shfl_xor_sync(0xffffffffu, a,  o);
            a2 += __shfl_xor_sync(0xffffffffu, a2, o);
        }
        if (lane == 0) { sh[0] = a; sh[1] = a2; }
    }
    __syncthreads();
    const float mean = sh[0] * (1.f/1024.f);
    const float var  = sh[1] * (1.f/1024.f) - mean*mean;
    const float rstd = 1.f / sqrtf(var + 1e-5f);
    const float4 gv = *(const float4*)(g  + tid*4);
    const float4 bv = *(const float4*)(bt + tid*4);
    float4 o;
    o.x = (xv.x - mean)*rstd*gv.x + bv.x;
    o.y = (xv.y - mean)*rstd*gv.y + bv.y;
    o.z = (xv.z - mean)*rstd*gv.z + bv.z;
    o.w = (xv.w - mean)*rstd*gv.w + bv.w;
    *(float4*)(x + off) = o;
    *(__half2*)(xh + off)     = __floats2half2_rn(o.x, o.y);
    *(__half2*)(xh + off + 2) = __floats2half2_rn(o.z, o.w);
}

// ---------------------------------------------------------------------------
// loss = mean((tgt[:,-1] @ W_ham^T + b_ham - (y - w_last))^2), fp32
// ---------------------------------------------------------------------------
__global__ void loss_kernel(const float* __restrict__ tgt, const float* __restrict__ Wh,
                            const float* __restrict__ bh, const float* __restrict__ y,
                            const float* __restrict__ w, float* __restrict__ out) {
    const int tid = threadIdx.x;
    float local = 0.f;
    for (int e = tid; e < 8*144; e += 256) {
        const int b = e / 144, j = e % 144;
        const float4* trow = (const float4*)(tgt + ((size_t)b*SS + SS-1)*DD);
        const float4* wr   = (const float4*)(Wh + (size_t)j*DD);
        float acc = bh[j];
        for (int k = 0; k < 256; k++) {
            const float4 a = trow[k], v = wr[k];
            acc += a.x*v.x + a.y*v.y + a.z*v.z + a.w*v.w;
        }
        const float resid = y[b*144 + j] - w[((size_t)b*16 + 15)*144 + j];
        const float d = acc - resid;
        local += d*d;
    }
    __shared__ float red[256];
    red[tid] = local; __syncthreads();
    for (int s = 128; s > 0; s >>= 1) {
        if (tid < s) red[tid] += red[tid+s];
        __syncthreads();
    }
    if (tid == 0) out[0] = red[0] / 1152.f;
}

// ---------------------------------------------------------------------------
extern "C" void kernel_launch(void* const* d_in, const int* in_sizes, int n_in,
                              void* d_out, int out_size) {
    (void)in_sizes; (void)n_in; (void)out_size;
    const float* x      = (const float*)d_in[0];
    const float* w      = (const float*)d_in[1];
    const float* y      = (const float*)d_in[2];
    const float* W_nail = (const float*)d_in[3];
    const float* b_nail = (const float*)d_in[4];
    const float* W_cond = (const float*)d_in[5];
    const float* b_cond = (const float*)d_in[6];
    const float* Wqkv   = (const float*)d_in[7];
    const float* bqkv   = (const float*)d_in[8];
    const float* Wo     = (const float*)d_in[9];
    const float* bo     = (const float*)d_in[10];
    const float* ln1_g  = (const float*)d_in[11];
    const float* ln1_b  = (const float*)d_in[12];
    const float* ln2_g  = (const float*)d_in[13];
    const float* ln2_b  = (const float*)d_in[14];
    const float* W1     = (const float*)d_in[15];
    const float* b1     = (const float*)d_in[16];
    const float* W2     = (const float*)d_in[17];
    const float* b2     = (const float*)d_in[18];
    const float* W_ham  = (const float*)d_in[19];
    const float* b_ham  = (const float*)d_in[20];

    float *tgt, *mid, *dv, *pet;
    __half *qh, *xh, *gh, *wh;
    cudaGetSymbolAddress((void**)&tgt, g_tgt);
    cudaGetSymbolAddress((void**)&mid, g_mid);
    cudaGetSymbolAddress((void**)&qh,  g_qh);
    cudaGetSymbolAddress((void**)&xh,  g_xh);
    cudaGetSymbolAddress((void**)&gh,  g_gh);
    cudaGetSymbolAddress((void**)&wh,  g_wh);
    cudaGetSymbolAddress((void**)&dv,  g_div);
    cudaGetSymbolAddress((void**)&pet, g_pet);

    cudaFuncSetAttribute(gemm_f16<0>, cudaFuncAttributeMaxDynamicSharedMemorySize, GEMM_SMEM);
    cudaFuncSetAttribute(gemm_f16<1>, cudaFuncAttributeMaxDynamicSharedMemorySize, GEMM_SMEM);
    cudaFuncSetAttribute(gemm_f16<2>, cudaFuncAttributeMaxDynamicSharedMemorySize, GEMM_SMEM);

    cvt_all_kernel<<<(N4_TOT+255)/256, 256>>>(Wqkv, Wo, W1, W2, wh);
    div_kernel<<<1, 512>>>(dv);
    pe_kernel<<<384, 256>>>(dv, pet);
    prep_kernel<<<MTOT, 256>>>(x, w, W_nail, b_nail, W_cond, b_cond, dv, pet, tgt, xh);

    for (int i = 0; i < NLAYERS; i++) {
        const __half* wq = wh + W_QKV_OFF + (size_t)i*3*DD*DD;
        const __half* wo = wh + W_O_OFF   + (size_t)i*DD*DD;
        const __half* w1 = wh + W_F1_OFF  + (size_t)i*FFD*DD;
        const __half* w2 = wh + W_F2_OFF  + (size_t)i*DD*FFD;
        const float* bqkv_i = bqkv + (size_t)i*3*DD;
        const float* bo_i   = bo   + (size_t)i*DD;
        const float* b1_i   = b1   + (size_t)i*FFD;
        const float* b2_i   = b2   + (size_t)i*DD;

        // qkv = x @ Wqkv^T + b  -> qh (fp16)
        gemm_f16<2><<<dim3(24, 56), 256, GEMM_SMEM>>>(xh, wq, bqkv_i, nullptr, qh, MTOT, 3*DD, DD);
        // attention -> xh (fp16, o-proj A operand)
        flash_attn_kernel<<<dim3(7, BB*NH), 128>>>(qh, xh);
        // o-proj -> mid (fp32)
        gemm_f16<0><<<dim3(8, 56), 256, GEMM_SMEM>>>(xh, wo, bo_i, mid, nullptr, MTOT, DD, DD);
        // tgt = LN(tgt + o); writes xh
        add_ln_kernel<<<MTOT, 256>>>(tgt, mid, ln1_g + (size_t)i*DD, ln1_b + (size_t)i*DD, xh);
        // ff1 + gelu -> gh (fp16)
        gemm_f16<1><<<dim3(32, 56), 256, GEMM_SMEM>>>(xh, w1, b1_i, nullptr, gh, MTOT, FFD, DD);
        // ff2 -> mid (fp32)
        gemm_f16<0><<<dim3(8, 56), 256, GEMM_SMEM>>>(gh, w2, b2_i, mid, nullptr, MTOT, DD, FFD);
        // tgt = LN(tgt + ff); writes xh
        add_ln_kernel<<<MTOT, 256>>>(tgt, mid, ln2_g + (size_t)i*DD, ln2_b + (size_t)i*DD, xh);
    }

    loss_kernel<<<1, 256>>>(tgt, W_ham, b_ham, y, w, (float*)d_out);
}

// round 14
// speedup vs baseline: 8.9282x; 2.0483x over previous
#include <cuda_runtime.h>
#include <cuda_fp16.h>
#include <math.h>
#include <stdint.h>

// Problem constants
#define BB 8
#define SS 896
#define LX 512
#define DD 1024
#define MTOT (BB*SS)    // 7168
#define NH 16
#define FFD 4096
#define NLAYERS 4

// fp16 weight buffer offsets (elements)
#define W_QKV_OFF 0
#define W_O_OFF   12582912
#define W_F1_OFF  16777216
#define W_F2_OFF  33554432
#define W_TOT     50331648

// Scratch (__device__ globals; allocation-free)
__device__ float  g_tgt[MTOT*DD];      // fp32 residual stream
__device__ float  g_mid[MTOT*DD];      // o-proj / ff2 fp32 outputs
__device__ __half g_qh[MTOT*3*DD];     // qkv fp16
__device__ __half g_xh[MTOT*DD];       // fp16 activation (GEMM A operand)
__device__ __half g_gh[MTOT*FFD];      // fp16 gelu intermediate
__device__ __half g_wh[W_TOT];         // fp16 weights
__device__ float  g_div[512];          // sinusoidal div table
__device__ float  g_pet[384*DD];       // exact PE for pos 512..895
__device__ float  g_wnt[63*DD];        // W_nail transposed [63][1024]

__device__ __forceinline__ uint32_t smem_u32(const void* p) {
    uint32_t a;
    asm("{ .reg .u64 t; cvta.to.shared.u64 t, %1; cvt.u32.u64 %0, t; }" : "=r"(a) : "l"(p));
    return a;
}

// ---------------------------------------------------------------------------
// Fused weight convert fp32 -> fp16 (all four weight tensors, one launch)
// ---------------------------------------------------------------------------
#define N4_QKV 3145728
#define N4_O   1048576
#define N4_F1  4194304
#define N4_F2  4194304
#define N4_TOT (N4_QKV+N4_O+N4_F1+N4_F2)

__global__ void cvt_all_kernel(const float* __restrict__ wq, const float* __restrict__ wo,
                               const float* __restrict__ w1, const float* __restrict__ w2,
                               __half* __restrict__ d) {
    int i = blockIdx.x * blockDim.x + threadIdx.x;
    if (i >= N4_TOT) return;
    const float* s; size_t off;
    if (i < N4_QKV)                 { s = wq; off = i;                       }
    else if (i < N4_QKV+N4_O)       { s = wo; off = i - N4_QKV;             }
    else if (i < N4_QKV+N4_O+N4_F1) { s = w1; off = i - (N4_QKV+N4_O);      }
    else                            { s = w2; off = i - (N4_QKV+N4_O+N4_F1);}
    float4 v = ((const float4*)s)[off];
    __half2 h0 = __floats2half2_rn(v.x, v.y);
    __half2 h1 = __floats2half2_rn(v.z, v.w);
    uint2 u;
    u.x = *(uint32_t*)&h0;
    u.y = *(uint32_t*)&h1;
    ((uint2*)d)[i] = u;
}

// ---------------------------------------------------------------------------
// Tables
// ---------------------------------------------------------------------------
__global__ void div_kernel(float* __restrict__ dv) {
    int i = threadIdx.x;   // 512
    dv[i] = expf((float)i * -0.0067458547646309937f);
}
__global__ void pe_kernel(const float* __restrict__ dv, float* __restrict__ pet) {
    const int pos = 512 + blockIdx.x;     // 512..895
    const int tid = threadIdx.x;          // 256
    #pragma unroll
    for (int it = 0; it < 4; it++) {
        const int d = tid + it*256;
        const float ang = (float)pos * dv[d >> 1];
        pet[blockIdx.x*DD + d] = (d & 1) ? cosf(ang) : sinf(ang);
    }
}
__global__ void wnt_kernel(const float* __restrict__ Wn, float* __restrict__ WnT) {
    int i = blockIdx.x * blockDim.x + threadIdx.x;   // 0..64511
    if (i >= 63*DD) return;
    int d = i / 63, k = i % 63;
    WnT[k*DD + d] = Wn[i];
}

// ---------------------------------------------------------------------------
// fp16 HMMA GEMM (unchanged from R10): C = A @ W^T + bias
// ---------------------------------------------------------------------------
#define GEMM_SMEM (3*32768)

template<int MODE>
__global__ __launch_bounds__(256, 2) void gemm_f16(
        const __half* __restrict__ A, const __half* __restrict__ B,
        const float* __restrict__ bias, float* __restrict__ Cf,
        __half* __restrict__ Ch, int M, int N, int K) {
    extern __shared__ char smem[];
    const uint32_t sb = smem_u32(smem);
    const int tid = threadIdx.x, lane = tid & 31, wid = tid >> 5;
    const int wm = wid & 1, wn = wid >> 1;
    const int m0 = blockIdx.y * 128, n0 = blockIdx.x * 128;

    float acc[4][4][4];
    #pragma unroll
    for (int a = 0; a < 4; a++)
        #pragma unroll
        for (int b = 0; b < 4; b++)
            #pragma unroll
            for (int cc = 0; cc < 4; cc++) acc[a][b][cc] = 0.f;

    auto load_chunk = [&](int c, int s) {
        const int k0 = c << 6;
        const uint32_t stg = sb + s * 32768;
        #pragma unroll
        for (int i = 0; i < 4; i++) {
            int u = tid + (i << 8);
            int row = u >> 3, cc = u & 7;
            uint32_t dA = stg + row * 128 + ((cc ^ (row & 7)) << 4);
            const void* gA = A + (size_t)(m0 + row) * K + k0 + cc * 8;
            asm volatile("cp.async.cg.shared.global [%0], [%1], 16;" :: "r"(dA), "l"(gA));
        }
        #pragma unroll
        for (int i = 0; i < 4; i++) {
            int u = tid + (i << 8);
            int row = u >> 3, cc = u & 7;
            uint32_t dB = stg + 16384 + row * 128 + ((cc ^ (row & 7)) << 4);
            const void* gB = B + (size_t)(n0 + row) * K + k0 + cc * 8;
            asm volatile("cp.async.cg.shared.global [%0], [%1], 16;" :: "r"(dB), "l"(gB));
        }
        asm volatile("cp.async.commit_group;" ::: "memory");
    };

    const int NC = K >> 6;
    load_chunk(0, 0);
    load_chunk(1, 1);
    int s3 = 0;
    for (int c = 0; c < NC; c++) {
        if (c + 1 < NC) asm volatile("cp.async.wait_group 1;" ::: "memory");
        else            asm volatile("cp.async.wait_group 0;" ::: "memory");
        __syncthreads();
        if (c + 2 < NC) {
            int sn = s3 + 2; if (sn >= 3) sn -= 3;
            load_chunk(c + 2, sn);
        }

        const uint32_t stg = sb + s3 * 32768;
        const uint32_t arow = stg + (wm * 64 + (lane & 15)) * 128;
        const uint32_t brow = stg + 16384
                            + (wn * 32 + ((lane >> 4) << 3) + (lane & 7)) * 128;
        const int ac = (lane >> 4), bc = ((lane >> 3) & 1), lx = lane & 7;

        #pragma unroll
        for (int ks = 0; ks < 4; ks++) {
            uint32_t a[4][4], b[4][2];
            const uint32_t axor = (uint32_t)(((2 * ks + ac) ^ lx) << 4);
            const uint32_t bxor = (uint32_t)(((2 * ks + bc) ^ lx) << 4);
            #pragma unroll
            for (int mt = 0; mt < 4; mt++) {
                asm volatile("ldmatrix.sync.aligned.m8n8.x4.shared.b16 {%0,%1,%2,%3}, [%4];"
                    : "=r"(a[mt][0]), "=r"(a[mt][1]), "=r"(a[mt][2]), "=r"(a[mt][3])
                    : "r"(arow + mt * 2048 + axor));
            }
            #pragma unroll
            for (int p = 0; p < 2; p++) {
                uint32_t r0, r1, r2, r3;
                asm volatile("ldmatrix.sync.aligned.m8n8.x4.shared.b16 {%0,%1,%2,%3}, [%4];"
                    : "=r"(r0), "=r"(r1), "=r"(r2), "=r"(r3)
                    : "r"(brow + p * 2048 + bxor));
                b[2*p][0] = r0; b[2*p][1] = r1; b[2*p+1][0] = r2; b[2*p+1][1] = r3;
            }
            #pragma unroll
            for (int mt = 0; mt < 4; mt++)
                #pragma unroll
                for (int nt = 0; nt < 4; nt++)
                    asm volatile(
                        "mma.sync.aligned.m16n8k16.row.col.f32.f16.f16.f32 "
                        "{%0,%1,%2,%3}, {%4,%5,%6,%7}, {%8,%9}, {%0,%1,%2,%3};"
                        : "+f"(acc[mt][nt][0]), "+f"(acc[mt][nt][1]),
                          "+f"(acc[mt][nt][2]), "+f"(acc[mt][nt][3])
                        : "r"(a[mt][0]), "r"(a[mt][1]), "r"(a[mt][2]), "r"(a[mt][3]),
                          "r"(b[nt][0]), "r"(b[nt][1]));
        }
        __syncthreads();
        s3++; if (s3 == 3) s3 = 0;
    }

    #pragma unroll
    for (int mt = 0; mt < 4; mt++) {
        const int m = m0 + wm * 64 + mt * 16 + (lane >> 2);
        #pragma unroll
        for (int nt = 0; nt < 4; nt++) {
            const int n = n0 + wn * 32 + nt * 8 + (lane & 3) * 2;
            const float b0 = bias[n], b1 = bias[n + 1];
            float v0 = acc[mt][nt][0] + b0, v1 = acc[mt][nt][1] + b1;
            float v2 = acc[mt][nt][2] + b0, v3 = acc[mt][nt][3] + b1;
            if (MODE == 1) {
                v0 = 0.5f * v0 * (1.0f + erff(v0 * 0.70710678118654752f));
                v1 = 0.5f * v1 * (1.0f + erff(v1 * 0.70710678118654752f));
                v2 = 0.5f * v2 * (1.0f + erff(v2 * 0.70710678118654752f));
                v3 = 0.5f * v3 * (1.0f + erff(v3 * 0.70710678118654752f));
            }
            if (MODE == 0) {
                float2 f01, f23;
                f01.x = v0; f01.y = v1; f23.x = v2; f23.y = v3;
                *(float2*)(Cf + (size_t)m * N + n)       = f01;
                *(float2*)(Cf + (size_t)(m + 8) * N + n) = f23;
            } else {
                *(__half2*)(Ch + (size_t)m * N + n)       = __floats2half2_rn(v0, v1);
                *(__half2*)(Ch + (size_t)(m + 8) * N + n) = __floats2half2_rn(v2, v3);
            }
        }
    }
}

// ---------------------------------------------------------------------------
// prep_x: x-region rows (4096). Tiled: 32 rows x 128 cols per block.
// tgt = f(x) @ WnT + bn + PE(t). f in smem (32x reuse of WnT traffic).
// ---------------------------------------------------------------------------
__global__ __launch_bounds__(256) void prep_x_kernel(
        const float* __restrict__ x, const float* __restrict__ WnT,
        const float* __restrict__ bn, const float* __restrict__ dv,
        float* __restrict__ tgt, __half* __restrict__ xh) {
    const int d0 = blockIdx.x * 128;      // 0..7 bands
    const int rt = blockIdx.y;            // 0..127 row tiles (32 rows)
    const int tid = threadIdx.x;
    __shared__ float f[32][64];           // f[r][k], k=0..62 valid
    __shared__ float sh_t[32];
    const float rs = 0.9999500037496877f;

    #pragma unroll
    for (int i = 0; i < 8; i++) {
        const int id = tid + i*256;       // 0..2047
        const int r = id >> 6, c = id & 63;
        float v = x[(size_t)(rt*32 + r)*64 + c];
        if (isnan(v)) v = 0.f;
        if (c == 0) sh_t[r] = v;
        else {
            v *= rs;
            f[r][c-1] = fminf(5.f, fmaxf(-5.f, v));
        }
    }
    __syncthreads();

    const int dloc = tid & 127, rh = tid >> 7;   // rh: 0/1 -> 16-row half
    const int d = d0 + dloc;
    float acc[16];
    #pragma unroll
    for (int r = 0; r < 16; r++) acc[r] = 0.f;
    #pragma unroll 7
    for (int k = 0; k < 63; k++) {
        const float wv = WnT[k*DD + d];
        #pragma unroll
        for (int r = 0; r < 16; r++) acc[r] += f[rh*16 + r][k] * wv;
    }
    const float bnv = bn[d];
    const float dvv = dv[d >> 1];
    const int odd = d & 1;
    #pragma unroll
    for (int r = 0; r < 16; r++) {
        const int xrow = rt*32 + rh*16 + r;
        const float ang = sh_t[rh*16 + r] * dvv;
        const float pe = odd ? __cosf(ang) : __sinf(ang);
        const float v = acc[r] + bnv + pe;
        const int b = xrow >> 9, s = xrow & 511;
        const size_t off = (size_t)(b*SS + s)*DD + d;
        tgt[off] = v;
        xh[off] = __float2half(v);
    }
}

// ---------------------------------------------------------------------------
// prep_w: w-region rows (3072), K=6 — cheap, per-row blocks.
// ---------------------------------------------------------------------------
__global__ void prep_w_kernel(const float* __restrict__ w,
                              const float* __restrict__ Wc, const float* __restrict__ bc,
                              const float* __restrict__ pet,
                              float* __restrict__ tgt, __half* __restrict__ xh) {
    const int blk = blockIdx.x;           // 0..3071
    const int b = blk / 384, j = blk % 384;
    const int row = b*SS + LX + j;
    const int tid = threadIdx.x;          // 256
    __shared__ float f[6];
    const float rs = 0.9999500037496877f;
    if (tid < 6) {
        float v = w[((size_t)b*384 + j)*6 + tid];
        if (isnan(v)) v = 0.f;
        v *= rs;
        f[tid] = fminf(5.f, fmaxf(-5.f, v));
    }
    __syncthreads();
    #pragma unroll
    for (int it = 0; it < 4; it++) {
        const int d = tid + it*256;
        float acc = bc[d];
        const float* wr = Wc + (size_t)d*6;
        #pragma unroll
        for (int k = 0; k < 6; k++) acc += f[k]*wr[k];
        acc += pet[(size_t)j*DD + d];
        tgt[(size_t)row*DD + d] = acc;
        xh[(size_t)row*DD + d] = __float2half(acc);
    }
}

// ---------------------------------------------------------------------------
// HMMA flash attention. qkv fp16 [B*S, 3072] = [q|k|v].
// Block: 64 q-rows x one (b,h); 4 warps (each 16 rows). KV tiles of 64.
// S = Q@K^T via mma (K non-trans ldmatrix), P@V via mma (V ldmatrix.trans).
// Online softmax in fragments, fp32 stats, __expf. Output fp16 -> xh.
// ---------------------------------------------------------------------------
#define AT_SMEM (8192*5)

__global__ __launch_bounds__(128) void flash_hmma(
        const __half* __restrict__ qkv, __half* __restrict__ xh) {
    extern __shared__ char smem[];
    const uint32_t sb = smem_u32(smem);
    const int q0 = blockIdx.x * 64;
    const int bh = blockIdx.y;
    const int b = bh >> 4, h = bh & 15;
    const int tid = threadIdx.x, lane = tid & 31, wid = tid >> 5;
    const __half* base = qkv + (size_t)b * SS * 3072;

    // async load Q tile (64x64) into sQ at sb
    #pragma unroll
    for (int i = 0; i < 4; i++) {
        const int id = tid + i*128;
        const int row = id >> 3, c = id & 7;
        const uint32_t dst = sb + row*128 + ((c ^ (row & 7)) << 4);
        const void* src = base + (size_t)(q0 + row)*3072 + h*64 + c*8;
        asm volatile("cp.async.cg.shared.global [%0], [%1], 16;" :: "r"(dst), "l"(src));
    }
    auto loadKV = [&](int kt, int s) {
        const int c0 = kt * 64;
        const uint32_t stg = sb + 8192 + s*16384;
        #pragma unroll
        for (int i = 0; i < 4; i++) {
            const int id = tid + i*128;
            const int row = id >> 3, c = id & 7;
            const uint32_t sw = ((c ^ (row & 7)) << 4);
            const void* srcK = base + (size_t)(c0 + row)*3072 + 1024 + h*64 + c*8;
            const void* srcV = base + (size_t)(c0 + row)*3072 + 2048 + h*64 + c*8;
            asm volatile("cp.async.cg.shared.global [%0], [%1], 16;" :: "r"(stg + row*128 + sw), "l"(srcK));
            asm volatile("cp.async.cg.shared.global [%0], [%1], 16;" :: "r"(stg + 8192 + row*128 + sw), "l"(srcV));
        }
        asm volatile("cp.async.commit_group;" ::: "memory");
    };
    loadKV(0, 0);   // committed together with Q (one group incl. Q cp.asyncs)

    const int ntiles = (q0 >= 512) ? (q0/64 + 1) : 8;

    float o[8][4];
    #pragma unroll
    for (int u = 0; u < 8; u++)
        #pragma unroll
        for (int e = 0; e < 4; e++) o[u][e] = 0.f;
    float m0 = -1e30f, m1 = -1e30f, l0 = 0.f, l1 = 0.f;
    uint32_t qa[4][4];

    const int lx = lane & 7;
    const int rbase = q0 + (wid << 4) + (lane >> 2);

    for (int kt = 0; kt < ntiles; kt++) {
        const int s = kt & 1;
        asm volatile("cp.async.wait_group 0;" ::: "memory");
        __syncthreads();
        if (kt == 0) {
            const uint32_t arow = sb + ((wid << 4) + (lane & 15)) * 128;
            const int ac = lane >> 4;
            #pragma unroll
            for (int ks = 0; ks < 4; ks++) {
                asm volatile("ldmatrix.sync.aligned.m8n8.x4.shared.b16 {%0,%1,%2,%3}, [%4];"
                    : "=r"(qa[ks][0]), "=r"(qa[ks][1]), "=r"(qa[ks][2]), "=r"(qa[ks][3])
                    : "r"(arow + ((uint32_t)((2*ks + ac) ^ lx) << 4)));
            }
        }
        if (kt + 1 < ntiles) loadKV(kt + 1, s ^ 1);

        const uint32_t stg = sb + 8192 + s*16384;
        // ---- S = Q @ K^T ----
        float sc[8][4];
        #pragma unroll
        for (int u = 0; u < 8; u++)
            #pragma unroll
            for (int e = 0; e < 4; e++) sc[u][e] = 0.f;
        {
            const uint32_t brow = stg + (((lane >> 4) << 3) + (lane & 7)) * 128;
            const int bc = (lane >> 3) & 1;
            #pragma unroll
            for (int ks = 0; ks < 4; ks++) {
                const uint32_t bxor = (uint32_t)(((2*ks + bc) ^ lx) << 4);
                #pragma unroll
                for (int p = 0; p < 4; p++) {
                    uint32_t r0, r1, r2, r3;
                    asm volatile("ldmatrix.sync.aligned.m8n8.x4.shared.b16 {%0,%1,%2,%3}, [%4];"
                        : "=r"(r0), "=r"(r1), "=r"(r2), "=r"(r3)
                        : "r"(brow + p * 2048 + bxor));
                    asm volatile(
                        "mma.sync.aligned.m16n8k16.row.col.f32.f16.f16.f32 "
                        "{%0,%1,%2,%3}, {%4,%5,%6,%7}, {%8,%9}, {%0,%1,%2,%3};"
                        : "+f"(sc[2*p][0]), "+f"(sc[2*p][1]), "+f"(sc[2*p][2]), "+f"(sc[2*p][3])
                        : "r"(qa[ks][0]), "r"(qa[ks][1]), "r"(qa[ks][2]), "r"(qa[ks][3]),
                          "r"(r0), "r"(r1));
                    asm volatile(
                        "mma.sync.aligned.m16n8k16.row.col.f32.f16.f16.f32 "
                        "{%0,%1,%2,%3}, {%4,%5,%6,%7}, {%8,%9}, {%0,%1,%2,%3};"
                        : "+f"(sc[2*p+1][0]), "+f"(sc[2*p+1][1]), "+f"(sc[2*p+1][2]), "+f"(sc[2*p+1][3])
                        : "r"(qa[ks][0]), "r"(qa[ks][1]), "r"(qa[ks][2]), "r"(qa[ks][3]),
                          "r"(r2), "r"(r3));
                }
            }
        }
        // ---- scale + mask ----
        const int c0 = kt * 64;
        const bool needMask = (c0 + 63 >= LX) && (c0 + 63 > q0);
        #pragma unroll
        for (int u = 0; u < 8; u++) {
            #pragma unroll
            for (int e = 0; e < 4; e++) {
                float v = sc[u][e] * 0.125f;
                if (needMask) {
                    const int c = c0 + u*8 + ((lane & 3) << 1) + (e & 1);
                    const int r = rbase + ((e >> 1) << 3);
                    if (c >= LX && c > r) v = -1e30f;
                }
                sc[u][e] = v;
            }
        }
        // ---- online softmax ----
        float rm0 = -1e30f, rm1 = -1e30f;
        #pragma unroll
        for (int u = 0; u < 8; u++) {
            rm0 = fmaxf(rm0, fmaxf(sc[u][0], sc[u][1]));
            rm1 = fmaxf(rm1, fmaxf(sc[u][2], sc[u][3]));
        }
        rm0 = fmaxf(rm0, __shfl_xor_sync(0xffffffffu, rm0, 1));
        rm0 = fmaxf(rm0, __shfl_xor_sync(0xffffffffu, rm0, 2));
        rm1 = fmaxf(rm1, __shfl_xor_sync(0xffffffffu, rm1, 1));
        rm1 = fmaxf(rm1, __shfl_xor_sync(0xffffffffu, rm1, 2));
        const float mn0 = fmaxf(m0, rm0), mn1 = fmaxf(m1, rm1);
        const float al0 = __expf(m0 - mn0), al1 = __expf(m1 - mn1);
        m0 = mn0; m1 = mn1;
        float ps0 = 0.f, ps1 = 0.f;
        #pragma unroll
        for (int u = 0; u < 8; u++) {
            float e0 = (sc[u][0] > -1e29f) ? __expf(sc[u][0] - mn0) : 0.f;
            float e1 = (sc[u][1] > -1e29f) ? __expf(sc[u][1] - mn0) : 0.f;
            float e2 = (sc[u][2] > -1e29f) ? __expf(sc[u][2] - mn1) : 0.f;
            float e3 = (sc[u][3] > -1e29f) ? __expf(sc[u][3] - mn1) : 0.f;
            sc[u][0] = e0; sc[u][1] = e1; sc[u][2] = e2; sc[u][3] = e3;
            ps0 += e0 + e1; ps1 += e2 + e3;
        }
        ps0 += __shfl_xor_sync(0xffffffffu, ps0, 1);
        ps0 += __shfl_xor_sync(0xffffffffu, ps0, 2);
        ps1 += __shfl_xor_sync(0xffffffffu, ps1, 1);
        ps1 += __shfl_xor_sync(0xffffffffu, ps1, 2);
        l0 = l0 * al0 + ps0;
        l1 = l1 * al1 + ps1;
        #pragma unroll
        for (int u = 0; u < 8; u++) {
            o[u][0] *= al0; o[u][1] *= al0; o[u][2] *= al1; o[u][3] *= al1;
        }
        // ---- O += P @ V ----
        const uint32_t vstg = stg + 8192;
        const int vrow_l = lane & 15;
        #pragma unroll
        for (int t = 0; t < 4; t++) {
            uint32_t pa0, pa1, pa2, pa3;
            {
                __half2 h0 = __floats2half2_rn(sc[2*t][0],   sc[2*t][1]);
                __half2 h1 = __floats2half2_rn(sc[2*t][2],   sc[2*t][3]);
                __half2 h2 = __floats2half2_rn(sc[2*t+1][0], sc[2*t+1][1]);
                __half2 h3 = __floats2half2_rn(sc[2*t+1][2], sc[2*t+1][3]);
                pa0 = *(uint32_t*)&h0; pa1 = *(uint32_t*)&h1;
                pa2 = *(uint32_t*)&h2; pa3 = *(uint32_t*)&h3;
            }
            const int vrow = t*16 + vrow_l;
            const uint32_t vbase = vstg + vrow*128;
            #pragma unroll
            for (int up = 0; up < 4; up++) {
                uint32_t v0, v1, v2, v3;
                const uint32_t chunk = (uint32_t)(2*up + (lane >> 4));
                asm volatile("ldmatrix.sync.aligned.m8n8.x4.trans.shared.b16 {%0,%1,%2,%3}, [%4];"
                    : "=r"(v0), "=r"(v1), "=r"(v2), "=r"(v3)
                    : "r"(vbase + ((chunk ^ (uint32_t)(vrow & 7)) << 4)));
                asm volatile(
                    "mma.sync.aligned.m16n8k16.row.col.f32.f16.f16.f32 "
                    "{%0,%1,%2,%3}, {%4,%5,%6,%7}, {%8,%9}, {%0,%1,%2,%3};"
                    : "+f"(o[2*up][0]), "+f"(o[2*up][1]), "+f"(o[2*up][2]), "+f"(o[2*up][3])
                    : "r"(pa0), "r"(pa1), "r"(pa2), "r"(pa3), "r"(v0), "r"(v1));
                asm volatile(
                    "mma.sync.aligned.m16n8k16.row.col.f32.f16.f16.f32 "
                    "{%0,%1,%2,%3}, {%4,%5,%6,%7}, {%8,%9}, {%0,%1,%2,%3};"
                    : "+f"(o[2*up+1][0]), "+f"(o[2*up+1][1]), "+f"(o[2*up+1][2]), "+f"(o[2*up+1][3])
                    : "r"(pa0), "r"(pa1), "r"(pa2), "r"(pa3), "r"(v2), "r"(v3));
            }
        }
    }

    // ---- normalize + store (fp16) ----
    const float inv0 = 1.f / l0, inv1 = 1.f / l1;
    const int orow0 = b*SS + q0 + (wid << 4) + (lane >> 2);
    const int colb = h*64 + ((lane & 3) << 1);
    #pragma unroll
    for (int u = 0; u < 8; u++) {
        *(__half2*)(xh + (size_t)orow0*DD + colb + u*8) =
            __floats2half2_rn(o[u][0]*inv0, o[u][1]*inv0);
        *(__half2*)(xh + (size_t)(orow0 + 8)*DD + colb + u*8) =
            __floats2half2_rn(o[u][2]*inv1, o[u][3]*inv1);
    }
}

// ---------------------------------------------------------------------------
// x = LayerNorm(x + r)*g + b (in-place, fp32) + fp16 copy
// ---------------------------------------------------------------------------
__global__ __launch_bounds__(256) void add_ln_kernel(
        float* __restrict__ x, const float* __restrict__ r,
        const float* __restrict__ g, const float* __restrict__ bt,
        __half* __restrict__ xh) {
    const int row = blockIdx.x;
    const int tid = threadIdx.x;
    const size_t off = (size_t)row*DD + tid*4;
    float4 xv = *(float4*)(x + off);
    const float4 rv = *(const float4*)(r + off);
    xv.x += rv.x; xv.y += rv.y; xv.z += rv.z; xv.w += rv.w;
    float s  = xv.x + xv.y + xv.z + xv.w;
    float s2 = xv.x*xv.x + xv.y*xv.y + xv.z*xv.z + xv.w*xv.w;
    __shared__ float sh[16];
    #pragma unroll
    for (int o = 16; o; o >>= 1) {
        s  += __shfl_xor_sync(0xffffffffu, s,  o);
        s2 += __shfl_xor_sync(0xffffffffu, s2, o);
    }
    const int warp = tid >> 5, lane = tid & 31;
    if (lane == 0) { sh[warp] = s; sh[warp+8] = s2; }
    __syncthreads();
    if (tid < 32) {
        float a  = (lane < 8) ? sh[lane]   : 0.f;
        float a2 = (lane < 8) ? sh[lane+8] : 0.f;
        #pragma unroll
        for (int o = 4; o; o >>= 1) {
            a  += __shfl_xor_sync(0xffffffffu, a,  o);
            a2 += __shfl_xor_sync(0xffffffffu, a2, o);
        }
        if (lane == 0) { sh[0] = a; sh[1] = a2; }
    }
    __syncthreads();
    const float mean = sh[0] * (1.f/1024.f);
    const float var  = sh[1] * (1.f/1024.f) - mean*mean;
    const float rstd = 1.f / sqrtf(var + 1e-5f);
    const float4 gv = *(const float4*)(g  + tid*4);
    const float4 bv = *(const float4*)(bt + tid*4);
    float4 o;
    o.x = (xv.x - mean)*rstd*gv.x + bv.x;
    o.y = (xv.y - mean)*rstd*gv.y + bv.y;
    o.z = (xv.z - mean)*rstd*gv.z + bv.z;
    o.w = (xv.w - mean)*rstd*gv.w + bv.w;
    *(float4*)(x + off) = o;
    *(__half2*)(xh + off)     = __floats2half2_rn(o.x, o.y);
    *(__half2*)(xh + off + 2) = __floats2half2_rn(o.z, o.w);
}

// ---------------------------------------------------------------------------
// loss
// ---------------------------------------------------------------------------
__global__ void loss_kernel(const float* __restrict__ tgt, const float* __restrict__ Wh,
                            const float* __restrict__ bh, const float* __restrict__ y,
                            const float* __restrict__ w, float* __restrict__ out) {
    const int tid = threadIdx.x;
    float local = 0.f;
    for (int e = tid; e < 8*144; e += 256) {
        const int b = e / 144, j = e % 144;
        const float4* trow = (const float4*)(tgt + ((size_t)b*SS + SS-1)*DD);
        const float4* wr   = (const float4*)(Wh + (size_t)j*DD);
        float acc = bh[j];
        for (int k = 0; k < 256; k++) {
            const float4 a = trow[k], v = wr[k];
            acc += a.x*v.x + a.y*v.y + a.z*v.z + a.w*v.w;
        }
        const float resid = y[b*144 + j] - w[((size_t)b*16 + 15)*144 + j];
        const float d = acc - resid;
        local += d*d;
    }
    __shared__ float red[256];
    red[tid] = local; __syncthreads();
    for (int s = 128; s > 0; s >>= 1) {
        if (tid < s) red[tid] += red[tid+s];
        __syncthreads();
    }
    if (tid == 0) out[0] = red[0] / 1152.f;
}

// ---------------------------------------------------------------------------
extern "C" void kernel_launch(void* const* d_in, const int* in_sizes, int n_in,
                              void* d_out, int out_size) {
    (void)in_sizes; (void)n_in; (void)out_size;
    const float* x      = (const float*)d_in[0];
    const float* w      = (const float*)d_in[1];
    const float* y      = (const float*)d_in[2];
    const float* W_nail = (const float*)d_in[3];
    const float* b_nail = (const float*)d_in[4];
    const float* W_cond = (const float*)d_in[5];
    const float* b_cond = (const float*)d_in[6];
    const float* Wqkv   = (const float*)d_in[7];
    const float* bqkv   = (const float*)d_in[8];
    const float* Wo     = (const float*)d_in[9];
    const float* bo     = (const float*)d_in[10];
    const float* ln1_g  = (const float*)d_in[11];
    const float* ln1_b  = (const float*)d_in[12];
    const float* ln2_g  = (const float*)d_in[13];
    const float* ln2_b  = (const float*)d_in[14];
    const float* W1     = (const float*)d_in[15];
    const float* b1     = (const float*)d_in[16];
    const float* W2     = (const float*)d_in[17];
    const float* b2     = (const float*)d_in[18];
    const float* W_ham  = (const float*)d_in[19];
    const float* b_ham  = (const float*)d_in[20];

    float *tgt, *mid, *dv, *pet, *wnt;
    __half *qh, *xh, *gh, *wh;
    cudaGetSymbolAddress((void**)&tgt, g_tgt);
    cudaGetSymbolAddress((void**)&mid, g_mid);
    cudaGetSymbolAddress((void**)&qh,  g_qh);
    cudaGetSymbolAddress((void**)&xh,  g_xh);
    cudaGetSymbolAddress((void**)&gh,  g_gh);
    cudaGetSymbolAddress((void**)&wh,  g_wh);
    cudaGetSymbolAddress((void**)&dv,  g_div);
    cudaGetSymbolAddress((void**)&pet, g_pet);
    cudaGetSymbolAddress((void**)&wnt, g_wnt);

    cudaFuncSetAttribute(gemm_f16<0>, cudaFuncAttributeMaxDynamicSharedMemorySize, GEMM_SMEM);
    cudaFuncSetAttribute(gemm_f16<1>, cudaFuncAttributeMaxDynamicSharedMemorySize, GEMM_SMEM);
    cudaFuncSetAttribute(gemm_f16<2>, cudaFuncAttributeMaxDynamicSharedMemorySize, GEMM_SMEM);
    cudaFuncSetAttribute(flash_hmma,  cudaFuncAttributeMaxDynamicSharedMemorySize, AT_SMEM);

    cvt_all_kernel<<<(N4_TOT+255)/256, 256>>>(Wqkv, Wo, W1, W2, wh);
    div_kernel<<<1, 512>>>(dv);
    pe_kernel<<<384, 256>>>(dv, pet);
    wnt_kernel<<<(63*DD+255)/256, 256>>>(W_nail, wnt);
    prep_x_kernel<<<dim3(8, 128), 256>>>(x, wnt, b_nail, dv, tgt, xh);
    prep_w_kernel<<<3072, 256>>>(w, W_cond, b_cond, pet, tgt, xh);

    for (int i = 0; i < NLAYERS; i++) {
        const __half* wq = wh + W_QKV_OFF + (size_t)i*3*DD*DD;
        const __half* wo = wh + W_O_OFF   + (size_t)i*DD*DD;
        const __half* w1 = wh + W_F1_OFF  + (size_t)i*FFD*DD;
        const __half* w2 = wh + W_F2_OFF  + (size_t)i*DD*FFD;
        const float* bqkv_i = bqkv + (size_t)i*3*DD;
        const float* bo_i   = bo   + (size_t)i*DD;
        const float* b1_i   = b1   + (size_t)i*FFD;
        const float* b2_i   = b2   + (size_t)i*DD;

        // qkv = x @ Wqkv^T + b  -> qh (fp16)
        gemm_f16<2><<<dim3(24, 56), 256, GEMM_SMEM>>>(xh, wq, bqkv_i, nullptr, qh, MTOT, 3*DD, DD);
        // attention -> xh (fp16)
        flash_hmma<<<dim3(14, BB*NH), 128, AT_SMEM>>>(qh, xh);
        // o-proj -> mid (fp32)
        gemm_f16<0><<<dim3(8, 56), 256, GEMM_SMEM>>>(xh, wo, bo_i, mid, nullptr, MTOT, DD, DD);
        // tgt = LN(tgt + o); writes xh
        add_ln_kernel<<<MTOT, 256>>>(tgt, mid, ln1_g + (size_t)i*DD, ln1_b + (size_t)i*DD, xh);
        // ff1 + gelu -> gh (fp16)
        gemm_f16<1><<<dim3(32, 56), 256, GEMM_SMEM>>>(xh, w1, b1_i, nullptr, gh, MTOT, FFD, DD);
        // ff2 -> mid (fp32)
        gemm_f16<0><<<dim3(8, 56), 256, GEMM_SMEM>>>(gh, w2, b2_i, mid, nullptr, MTOT, DD, FFD);
        // tgt = LN(tgt + ff); writes xh
        add_ln_kernel<<<MTOT, 256>>>(tgt, mid, ln2_g + (size_t)i*DD, ln2_b + (size_t)i*DD, xh);
    }

    loss_kernel<<<1, 256>>>(tgt, W_ham, b_ham, y, w, (float*)d_out);
}

// round 15
// speedup vs baseline: 9.9189x; 1.1110x over previous
#include <cuda_runtime.h>
#include <cuda_fp16.h>
#include <math.h>
#include <stdint.h>

// Problem constants
#define BB 8
#define SS 896
#define LX 512
#define DD 1024
#define MTOT (BB*SS)    // 7168
#define NH 16
#define FFD 4096
#define NLAYERS 4

// fp16 weight buffer offsets (elements)
#define W_QKV_OFF 0
#define W_O_OFF   12582912
#define W_F1_OFF  16777216
#define W_F2_OFF  33554432
#define W_TOT     50331648

// Scratch (__device__ globals; allocation-free)
__device__ float  g_tgt[MTOT*DD];      // fp32 residual stream
__device__ float  g_mid[MTOT*DD];      // o-proj / ff2 fp32 outputs
__device__ __half g_qh[MTOT*3*DD];     // qkv fp16
__device__ __half g_xh[MTOT*DD];       // fp16 activation (GEMM A operand)
__device__ __half g_gh[MTOT*FFD];      // fp16 gelu intermediate
__device__ __half g_wh[W_TOT];         // fp16 weights
__device__ float  g_div[512];          // sinusoidal div table
__device__ float  g_pet[384*DD];       // exact PE for pos 512..895
__device__ float  g_wnt[63*DD];        // W_nail transposed [63][1024]
__device__ float  g_lpart[72];         // loss partials

__device__ __forceinline__ uint32_t smem_u32(const void* p) {
    uint32_t a;
    asm("{ .reg .u64 t; cvta.to.shared.u64 t, %1; cvt.u32.u64 %0, t; }" : "=r"(a) : "l"(p));
    return a;
}

// ---------------------------------------------------------------------------
// Fused weight convert fp32 -> fp16 (all four weight tensors, one launch)
// ---------------------------------------------------------------------------
#define N4_QKV 3145728
#define N4_O   1048576
#define N4_F1  4194304
#define N4_F2  4194304
#define N4_TOT (N4_QKV+N4_O+N4_F1+N4_F2)

__global__ void cvt_all_kernel(const float* __restrict__ wq, const float* __restrict__ wo,
                               const float* __restrict__ w1, const float* __restrict__ w2,
                               __half* __restrict__ d) {
    int i = blockIdx.x * blockDim.x + threadIdx.x;
    if (i >= N4_TOT) return;
    const float* s; size_t off;
    if (i < N4_QKV)                 { s = wq; off = i;                       }
    else if (i < N4_QKV+N4_O)       { s = wo; off = i - N4_QKV;             }
    else if (i < N4_QKV+N4_O+N4_F1) { s = w1; off = i - (N4_QKV+N4_O);      }
    else                            { s = w2; off = i - (N4_QKV+N4_O+N4_F1);}
    float4 v = ((const float4*)s)[off];
    __half2 h0 = __floats2half2_rn(v.x, v.y);
    __half2 h1 = __floats2half2_rn(v.z, v.w);
    uint2 u;
    u.x = *(uint32_t*)&h0;
    u.y = *(uint32_t*)&h1;
    ((uint2*)d)[i] = u;
}

// ---------------------------------------------------------------------------
// Tables
// ---------------------------------------------------------------------------
__global__ void div_kernel(float* __restrict__ dv) {
    int i = threadIdx.x;   // 512
    dv[i] = expf((float)i * -0.0067458547646309937f);
}
__global__ void pe_kernel(const float* __restrict__ dv, float* __restrict__ pet) {
    const int pos = 512 + blockIdx.x;     // 512..895
    const int tid = threadIdx.x;          // 256
    #pragma unroll
    for (int it = 0; it < 4; it++) {
        const int d = tid + it*256;
        const float ang = (float)pos * dv[d >> 1];
        pet[blockIdx.x*DD + d] = (d & 1) ? cosf(ang) : sinf(ang);
    }
}
__global__ void wnt_kernel(const float* __restrict__ Wn, float* __restrict__ WnT) {
    int i = blockIdx.x * blockDim.x + threadIdx.x;   // 0..64511
    if (i >= 63*DD) return;
    int d = i / 63, k = i % 63;
    WnT[k*DD + d] = Wn[i];
}

// ---------------------------------------------------------------------------
// fp16 HMMA GEMM: C = A @ W^T + bias.
// 128x128 CTA tile, 4 warps (2x2), 64x64 warp tile, BK=64, 3-stage cp.async.
// 2 CTAs/SM. MODE 0: fp32 out. MODE 1: GELU, fp16 out. MODE 2: fp16 out.
// ---------------------------------------------------------------------------
#define GEMM_SMEM (3*32768)

template<int MODE>
__global__ __launch_bounds__(128, 2) void gemm_f16(
        const __half* __restrict__ A, const __half* __restrict__ B,
        const float* __restrict__ bias, float* __restrict__ Cf,
        __half* __restrict__ Ch, int M, int N, int K) {
    extern __shared__ char smem[];
    const uint32_t sb = smem_u32(smem);
    const int tid = threadIdx.x, lane = tid & 31, wid = tid >> 5;
    const int wm = wid & 1, wn = wid >> 1;          // 2 x 2 warp grid
    const int m0 = blockIdx.y * 128, n0 = blockIdx.x * 128;

    float acc[4][8][4];
    #pragma unroll
    for (int a = 0; a < 4; a++)
        #pragma unroll
        for (int b = 0; b < 8; b++)
            #pragma unroll
            for (int cc = 0; cc < 4; cc++) acc[a][b][cc] = 0.f;

    auto load_chunk = [&](int c, int s) {
        const int k0 = c << 6;
        const uint32_t stg = sb + s * 32768;
        #pragma unroll
        for (int i = 0; i < 8; i++) {
            int u = tid + (i << 7);
            int row = u >> 3, cc = u & 7;
            uint32_t dA = stg + row * 128 + ((cc ^ (row & 7)) << 4);
            const void* gA = A + (size_t)(m0 + row) * K + k0 + cc * 8;
            asm volatile("cp.async.cg.shared.global [%0], [%1], 16;" :: "r"(dA), "l"(gA));
        }
        #pragma unroll
        for (int i = 0; i < 8; i++) {
            int u = tid + (i << 7);
            int row = u >> 3, cc = u & 7;
            uint32_t dB = stg + 16384 + row * 128 + ((cc ^ (row & 7)) << 4);
            const void* gB = B + (size_t)(n0 + row) * K + k0 + cc * 8;
            asm volatile("cp.async.cg.shared.global [%0], [%1], 16;" :: "r"(dB), "l"(gB));
        }
        asm volatile("cp.async.commit_group;" ::: "memory");
    };

    const int NC = K >> 6;
    load_chunk(0, 0);
    load_chunk(1, 1);
    int s3 = 0;
    for (int c = 0; c < NC; c++) {
        if (c + 1 < NC) asm volatile("cp.async.wait_group 1;" ::: "memory");
        else            asm volatile("cp.async.wait_group 0;" ::: "memory");
        __syncthreads();
        if (c + 2 < NC) {
            int sn = s3 + 2; if (sn >= 3) sn -= 3;
            load_chunk(c + 2, sn);
        }

        const uint32_t stg = sb + s3 * 32768;
        const uint32_t arow = stg + (wm * 64 + (lane & 15)) * 128;
        const uint32_t brow = stg + 16384
                            + (wn * 64 + ((lane >> 4) << 3) + (lane & 7)) * 128;
        const int ac = (lane >> 4), bc = ((lane >> 3) & 1), lx = lane & 7;

        #pragma unroll
        for (int ks = 0; ks < 4; ks++) {
            uint32_t a[4][4], b[8][2];
            const uint32_t axor = (uint32_t)(((2 * ks + ac) ^ lx) << 4);
            const uint32_t bxor = (uint32_t)(((2 * ks + bc) ^ lx) << 4);
            #pragma unroll
            for (int mt = 0; mt < 4; mt++) {
                asm volatile("ldmatrix.sync.aligned.m8n8.x4.shared.b16 {%0,%1,%2,%3}, [%4];"
                    : "=r"(a[mt][0]), "=r"(a[mt][1]), "=r"(a[mt][2]), "=r"(a[mt][3])
                    : "r"(arow + mt * 2048 + axor));
            }
            #pragma unroll
            for (int p = 0; p < 4; p++) {
                uint32_t r0, r1, r2, r3;
                asm volatile("ldmatrix.sync.aligned.m8n8.x4.shared.b16 {%0,%1,%2,%3}, [%4];"
                    : "=r"(r0), "=r"(r1), "=r"(r2), "=r"(r3)
                    : "r"(brow + p * 2048 + bxor));
                b[2*p][0] = r0; b[2*p][1] = r1; b[2*p+1][0] = r2; b[2*p+1][1] = r3;
            }
            #pragma unroll
            for (int mt = 0; mt < 4; mt++)
                #pragma unroll
                for (int nt = 0; nt < 8; nt++)
                    asm volatile(
                        "mma.sync.aligned.m16n8k16.row.col.f32.f16.f16.f32 "
                        "{%0,%1,%2,%3}, {%4,%5,%6,%7}, {%8,%9}, {%0,%1,%2,%3};"
                        : "+f"(acc[mt][nt][0]), "+f"(acc[mt][nt][1]),
                          "+f"(acc[mt][nt][2]), "+f"(acc[mt][nt][3])
                        : "r"(a[mt][0]), "r"(a[mt][1]), "r"(a[mt][2]), "r"(a[mt][3]),
                          "r"(b[nt][0]), "r"(b[nt][1]));
        }
        __syncthreads();
        s3++; if (s3 == 3) s3 = 0;
    }

    // Epilogue (register -> global, fused bias/GELU/fp16)
    #pragma unroll
    for (int mt = 0; mt < 4; mt++) {
        const int m = m0 + wm * 64 + mt * 16 + (lane >> 2);
        #pragma unroll
        for (int nt = 0; nt < 8; nt++) {
            const int n = n0 + wn * 64 + nt * 8 + (lane & 3) * 2;
            const float b0 = bias[n], b1 = bias[n + 1];
            float v0 = acc[mt][nt][0] + b0, v1 = acc[mt][nt][1] + b1;
            float v2 = acc[mt][nt][2] + b0, v3 = acc[mt][nt][3] + b1;
            if (MODE == 1) {
                v0 = 0.5f * v0 * (1.0f + erff(v0 * 0.70710678118654752f));
                v1 = 0.5f * v1 * (1.0f + erff(v1 * 0.70710678118654752f));
                v2 = 0.5f * v2 * (1.0f + erff(v2 * 0.70710678118654752f));
                v3 = 0.5f * v3 * (1.0f + erff(v3 * 0.70710678118654752f));
            }
            if (MODE == 0) {
                float2 f01, f23;
                f01.x = v0; f01.y = v1; f23.x = v2; f23.y = v3;
                *(float2*)(Cf + (size_t)m * N + n)       = f01;
                *(float2*)(Cf + (size_t)(m + 8) * N + n) = f23;
            } else {
                *(__half2*)(Ch + (size_t)m * N + n)       = __floats2half2_rn(v0, v1);
                *(__half2*)(Ch + (size_t)(m + 8) * N + n) = __floats2half2_rn(v2, v3);
            }
        }
    }
}

// ---------------------------------------------------------------------------
// prep_x: x-region rows (4096). Tiled: 32 rows x 128 cols per block.
// ---------------------------------------------------------------------------
__global__ __launch_bounds__(256) void prep_x_kernel(
        const float* __restrict__ x, const float* __restrict__ WnT,
        const float* __restrict__ bn, const float* __restrict__ dv,
        float* __restrict__ tgt, __half* __restrict__ xh) {
    const int d0 = blockIdx.x * 128;
    const int rt = blockIdx.y;
    const int tid = threadIdx.x;
    __shared__ float f[32][64];
    __shared__ float sh_t[32];
    const float rs = 0.9999500037496877f;

    #pragma unroll
    for (int i = 0; i < 8; i++) {
        const int id = tid + i*256;
        const int r = id >> 6, c = id & 63;
        float v = x[(size_t)(rt*32 + r)*64 + c];
        if (isnan(v)) v = 0.f;
        if (c == 0) sh_t[r] = v;
        else {
            v *= rs;
            f[r][c-1] = fminf(5.f, fmaxf(-5.f, v));
        }
    }
    __syncthreads();

    const int dloc = tid & 127, rh = tid >> 7;
    const int d = d0 + dloc;
    float acc[16];
    #pragma unroll
    for (int r = 0; r < 16; r++) acc[r] = 0.f;
    #pragma unroll 7
    for (int k = 0; k < 63; k++) {
        const float wv = WnT[k*DD + d];
        #pragma unroll
        for (int r = 0; r < 16; r++) acc[r] += f[rh*16 + r][k] * wv;
    }
    const float bnv = bn[d];
    const float dvv = dv[d >> 1];
    const int odd = d & 1;
    #pragma unroll
    for (int r = 0; r < 16; r++) {
        const int xrow = rt*32 + rh*16 + r;
        const float ang = sh_t[rh*16 + r] * dvv;
        const float pe = odd ? __cosf(ang) : __sinf(ang);
        const float v = acc[r] + bnv + pe;
        const int b = xrow >> 9, s = xrow & 511;
        const size_t off = (size_t)(b*SS + s)*DD + d;
        tgt[off] = v;
        xh[off] = __float2half(v);
    }
}

// ---------------------------------------------------------------------------
// prep_w: w-region rows (3072), K=6.
// ---------------------------------------------------------------------------
__global__ void prep_w_kernel(const float* __restrict__ w,
                              const float* __restrict__ Wc, const float* __restrict__ bc,
                              const float* __restrict__ pet,
                              float* __restrict__ tgt, __half* __restrict__ xh) {
    const int blk = blockIdx.x;
    const int b = blk / 384, j = blk % 384;
    const int row = b*SS + LX + j;
    const int tid = threadIdx.x;
    __shared__ float f[6];
    const float rs = 0.9999500037496877f;
    if (tid < 6) {
        float v = w[((size_t)b*384 + j)*6 + tid];
        if (isnan(v)) v = 0.f;
        v *= rs;
        f[tid] = fminf(5.f, fmaxf(-5.f, v));
    }
    __syncthreads();
    #pragma unroll
    for (int it = 0; it < 4; it++) {
        const int d = tid + it*256;
        float acc = bc[d];
        const float* wr = Wc + (size_t)d*6;
        #pragma unroll
        for (int k = 0; k < 6; k++) acc += f[k]*wr[k];
        acc += pet[(size_t)j*DD + d];
        tgt[(size_t)row*DD + d] = acc;
        xh[(size_t)row*DD + d] = __float2half(acc);
    }
}

// ---------------------------------------------------------------------------
// HMMA flash attention (unchanged from R13).
// ---------------------------------------------------------------------------
#define AT_SMEM (8192*5)

__global__ __launch_bounds__(128) void flash_hmma(
        const __half* __restrict__ qkv, __half* __restrict__ xh) {
    extern __shared__ char smem[];
    const uint32_t sb = smem_u32(smem);
    const int q0 = blockIdx.x * 64;
    const int bh = blockIdx.y;
    const int b = bh >> 4, h = bh & 15;
    const int tid = threadIdx.x, lane = tid & 31, wid = tid >> 5;
    const __half* base = qkv + (size_t)b * SS * 3072;

    #pragma unroll
    for (int i = 0; i < 4; i++) {
        const int id = tid + i*128;
        const int row = id >> 3, c = id & 7;
        const uint32_t dst = sb + row*128 + ((c ^ (row & 7)) << 4);
        const void* src = base + (size_t)(q0 + row)*3072 + h*64 + c*8;
        asm volatile("cp.async.cg.shared.global [%0], [%1], 16;" :: "r"(dst), "l"(src));
    }
    auto loadKV = [&](int kt, int s) {
        const int c0 = kt * 64;
        const uint32_t stg = sb + 8192 + s*16384;
        #pragma unroll
        for (int i = 0; i < 4; i++) {
            const int id = tid + i*128;
            const int row = id >> 3, c = id & 7;
            const uint32_t sw = ((c ^ (row & 7)) << 4);
            const void* srcK = base + (size_t)(c0 + row)*3072 + 1024 + h*64 + c*8;
            const void* srcV = base + (size_t)(c0 + row)*3072 + 2048 + h*64 + c*8;
            asm volatile("cp.async.cg.shared.global [%0], [%1], 16;" :: "r"(stg + row*128 + sw), "l"(srcK));
            asm volatile("cp.async.cg.shared.global [%0], [%1], 16;" :: "r"(stg + 8192 + row*128 + sw), "l"(srcV));
        }
        asm volatile("cp.async.commit_group;" ::: "memory");
    };
    loadKV(0, 0);

    const int ntiles = (q0 >= 512) ? (q0/64 + 1) : 8;

    float o[8][4];
    #pragma unroll
    for (int u = 0; u < 8; u++)
        #pragma unroll
        for (int e = 0; e < 4; e++) o[u][e] = 0.f;
    float m0 = -1e30f, m1 = -1e30f, l0 = 0.f, l1 = 0.f;
    uint32_t qa[4][4];

    const int lx = lane & 7;
    const int rbase = q0 + (wid << 4) + (lane >> 2);

    for (int kt = 0; kt < ntiles; kt++) {
        const int s = kt & 1;
        asm volatile("cp.async.wait_group 0;" ::: "memory");
        __syncthreads();
        if (kt == 0) {
            const uint32_t arow = sb + ((wid << 4) + (lane & 15)) * 128;
            const int ac = lane >> 4;
            #pragma unroll
            for (int ks = 0; ks < 4; ks++) {
                asm volatile("ldmatrix.sync.aligned.m8n8.x4.shared.b16 {%0,%1,%2,%3}, [%4];"
                    : "=r"(qa[ks][0]), "=r"(qa[ks][1]), "=r"(qa[ks][2]), "=r"(qa[ks][3])
                    : "r"(arow + ((uint32_t)((2*ks + ac) ^ lx) << 4)));
            }
        }
        if (kt + 1 < ntiles) loadKV(kt + 1, s ^ 1);

        const uint32_t stg = sb + 8192 + s*16384;
        float sc[8][4];
        #pragma unroll
        for (int u = 0; u < 8; u++)
            #pragma unroll
            for (int e = 0; e < 4; e++) sc[u][e] = 0.f;
        {
            const uint32_t brow = stg + (((lane >> 4) << 3) + (lane & 7)) * 128;
            const int bc = (lane >> 3) & 1;
            #pragma unroll
            for (int ks = 0; ks < 4; ks++) {
                const uint32_t bxor = (uint32_t)(((2*ks + bc) ^ lx) << 4);
                #pragma unroll
                for (int p = 0; p < 4; p++) {
                    uint32_t r0, r1, r2, r3;
                    asm volatile("ldmatrix.sync.aligned.m8n8.x4.shared.b16 {%0,%1,%2,%3}, [%4];"
                        : "=r"(r0), "=r"(r1), "=r"(r2), "=r"(r3)
                        : "r"(brow + p * 2048 + bxor));
                    asm volatile(
                        "mma.sync.aligned.m16n8k16.row.col.f32.f16.f16.f32 "
                        "{%0,%1,%2,%3}, {%4,%5,%6,%7}, {%8,%9}, {%0,%1,%2,%3};"
                        : "+f"(sc[2*p][0]), "+f"(sc[2*p][1]), "+f"(sc[2*p][2]), "+f"(sc[2*p][3])
                        : "r"(qa[ks][0]), "r"(qa[ks][1]), "r"(qa[ks][2]), "r"(qa[ks][3]),
                          "r"(r0), "r"(r1));
                    asm volatile(
                        "mma.sync.aligned.m16n8k16.row.col.f32.f16.f16.f32 "
                        "{%0,%1,%2,%3}, {%4,%5,%6,%7}, {%8,%9}, {%0,%1,%2,%3};"
                        : "+f"(sc[2*p+1][0]), "+f"(sc[2*p+1][1]), "+f"(sc[2*p+1][2]), "+f"(sc[2*p+1][3])
                        : "r"(qa[ks][0]), "r"(qa[ks][1]), "r"(qa[ks][2]), "r"(qa[ks][3]),
                          "r"(r2), "r"(r3));
                }
            }
        }
        const int c0 = kt * 64;
        const bool needMask = (c0 + 63 >= LX) && (c0 + 63 > q0);
        #pragma unroll
        for (int u = 0; u < 8; u++) {
            #pragma unroll
            for (int e = 0; e < 4; e++) {
                float v = sc[u][e] * 0.125f;
                if (needMask) {
                    const int c = c0 + u*8 + ((lane & 3) << 1) + (e & 1);
                    const int r = rbase + ((e >> 1) << 3);
                    if (c >= LX && c > r) v = -1e30f;
                }
                sc[u][e] = v;
            }
        }
        float rm0 = -1e30f, rm1 = -1e30f;
        #pragma unroll
        for (int u = 0; u < 8; u++) {
            rm0 = fmaxf(rm0, fmaxf(sc[u][0], sc[u][1]));
            rm1 = fmaxf(rm1, fmaxf(sc[u][2], sc[u][3]));
        }
        rm0 = fmaxf(rm0, __shfl_xor_sync(0xffffffffu, rm0, 1));
        rm0 = fmaxf(rm0, __shfl_xor_sync(0xffffffffu, rm0, 2));
        rm1 = fmaxf(rm1, __shfl_xor_sync(0xffffffffu, rm1, 1));
        rm1 = fmaxf(rm1, __shfl_xor_sync(0xffffffffu, rm1, 2));
        const float mn0 = fmaxf(m0, rm0), mn1 = fmaxf(m1, rm1);
        const float al0 = __expf(m0 - mn0), al1 = __expf(m1 - mn1);
        m0 = mn0; m1 = mn1;
        float ps0 = 0.f, ps1 = 0.f;
        #pragma unroll
        for (int u = 0; u < 8; u++) {
            float e0 = (sc[u][0] > -1e29f) ? __expf(sc[u][0] - mn0) : 0.f;
            float e1 = (sc[u][1] > -1e29f) ? __expf(sc[u][1] - mn0) : 0.f;
            float e2 = (sc[u][2] > -1e29f) ? __expf(sc[u][2] - mn1) : 0.f;
            float e3 = (sc[u][3] > -1e29f) ? __expf(sc[u][3] - mn1) : 0.f;
            sc[u][0] = e0; sc[u][1] = e1; sc[u][2] = e2; sc[u][3] = e3;
            ps0 += e0 + e1; ps1 += e2 + e3;
        }
        ps0 += __shfl_xor_sync(0xffffffffu, ps0, 1);
        ps0 += __shfl_xor_sync(0xffffffffu, ps0, 2);
        ps1 += __shfl_xor_sync(0xffffffffu, ps1, 1);
        ps1 += __shfl_xor_sync(0xffffffffu, ps1, 2);
        l0 = l0 * al0 + ps0;
        l1 = l1 * al1 + ps1;
        #pragma unroll
        for (int u = 0; u < 8; u++) {
            o[u][0] *= al0; o[u][1] *= al0; o[u][2] *= al1; o[u][3] *= al1;
        }
        const uint32_t vstg = stg + 8192;
        const int vrow_l = lane & 15;
        #pragma unroll
        for (int t = 0; t < 4; t++) {
            uint32_t pa0, pa1, pa2, pa3;
            {
                __half2 h0 = __floats2half2_rn(sc[2*t][0],   sc[2*t][1]);
                __half2 h1 = __floats2half2_rn(sc[2*t][2],   sc[2*t][3]);
                __half2 h2 = __floats2half2_rn(sc[2*t+1][0], sc[2*t+1][1]);
                __half2 h3 = __floats2half2_rn(sc[2*t+1][2], sc[2*t+1][3]);
                pa0 = *(uint32_t*)&h0; pa1 = *(uint32_t*)&h1;
                pa2 = *(uint32_t*)&h2; pa3 = *(uint32_t*)&h3;
            }
            const int vrow = t*16 + vrow_l;
            const uint32_t vbase = vstg + vrow*128;
            #pragma unroll
            for (int up = 0; up < 4; up++) {
                uint32_t v0, v1, v2, v3;
                const uint32_t chunk = (uint32_t)(2*up + (lane >> 4));
                asm volatile("ldmatrix.sync.aligned.m8n8.x4.trans.shared.b16 {%0,%1,%2,%3}, [%4];"
                    : "=r"(v0), "=r"(v1), "=r"(v2), "=r"(v3)
                    : "r"(vbase + ((chunk ^ (uint32_t)(vrow & 7)) << 4)));
                asm volatile(
                    "mma.sync.aligned.m16n8k16.row.col.f32.f16.f16.f32 "
                    "{%0,%1,%2,%3}, {%4,%5,%6,%7}, {%8,%9}, {%0,%1,%2,%3};"
                    : "+f"(o[2*up][0]), "+f"(o[2*up][1]), "+f"(o[2*up][2]), "+f"(o[2*up][3])
                    : "r"(pa0), "r"(pa1), "r"(pa2), "r"(pa3), "r"(v0), "r"(v1));
                asm volatile(
                    "mma.sync.aligned.m16n8k16.row.col.f32.f16.f16.f32 "
                    "{%0,%1,%2,%3}, {%4,%5,%6,%7}, {%8,%9}, {%0,%1,%2,%3};"
                    : "+f"(o[2*up+1][0]), "+f"(o[2*up+1][1]), "+f"(o[2*up+1][2]), "+f"(o[2*up+1][3])
                    : "r"(pa0), "r"(pa1), "r"(pa2), "r"(pa3), "r"(v2), "r"(v3));
            }
        }
    }

    const float inv0 = 1.f / l0, inv1 = 1.f / l1;
    const int orow0 = b*SS + q0 + (wid << 4) + (lane >> 2);
    const int colb = h*64 + ((lane & 3) << 1);
    #pragma unroll
    for (int u = 0; u < 8; u++) {
        *(__half2*)(xh + (size_t)orow0*DD + colb + u*8) =
            __floats2half2_rn(o[u][0]*inv0, o[u][1]*inv0);
        *(__half2*)(xh + (size_t)(orow0 + 8)*DD + colb + u*8) =
            __floats2half2_rn(o[u][2]*inv1, o[u][3]*inv1);
    }
}

// ---------------------------------------------------------------------------
// x = LayerNorm(x + r)*g + b (in-place, fp32) + fp16 copy
// ---------------------------------------------------------------------------
__global__ __launch_bounds__(256) void add_ln_kernel(
        float* __restrict__ x, const float* __restrict__ r,
        const float* __restrict__ g, const float* __restrict__ bt,
        __half* __restrict__ xh) {
    const int row = blockIdx.x;
    const int tid = threadIdx.x;
    const size_t off = (size_t)row*DD + tid*4;
    float4 xv = *(float4*)(x + off);
    const float4 rv = *(const float4*)(r + off);
    xv.x += rv.x; xv.y += rv.y; xv.z += rv.z; xv.w += rv.w;
    float s  = xv.x + xv.y + xv.z + xv.w;
    float s2 = xv.x*xv.x + xv.y*xv.y + xv.z*xv.z + xv.w*xv.w;
    __shared__ float sh[16];
    #pragma unroll
    for (int o = 16; o; o >>= 1) {
        s  += __shfl_xor_sync(0xffffffffu, s,  o);
        s2 += __shfl_xor_sync(0xffffffffu, s2, o);
    }
    const int warp = tid >> 5, lane = tid & 31;
    if (lane == 0) { sh[warp] = s; sh[warp+8] = s2; }
    __syncthreads();
    if (tid < 32) {
        float a  = (lane < 8) ? sh[lane]   : 0.f;
        float a2 = (lane < 8) ? sh[lane+8] : 0.f;
        #pragma unroll
        for (int o = 4; o; o >>= 1) {
            a  += __shfl_xor_sync(0xffffffffu, a,  o);
            a2 += __shfl_xor_sync(0xffffffffu, a2, o);
        }
        if (lane == 0) { sh[0] = a; sh[1] = a2; }
    }
    __syncthreads();
    const float mean = sh[0] * (1.f/1024.f);
    const float var  = sh[1] * (1.f/1024.f) - mean*mean;
    const float rstd = 1.f / sqrtf(var + 1e-5f);
    const float4 gv = *(const float4*)(g  + tid*4);
    const float4 bv = *(const float4*)(bt + tid*4);
    float4 o;
    o.x = (xv.x - mean)*rstd*gv.x + bv.x;
    o.y = (xv.y - mean)*rstd*gv.y + bv.y;
    o.z = (xv.z - mean)*rstd*gv.z + bv.z;
    o.w = (xv.w - mean)*rstd*gv.w + bv.w;
    *(float4*)(x + off) = o;
    *(__half2*)(xh + off)     = __floats2half2_rn(o.x, o.y);
    *(__half2*)(xh + off + 2) = __floats2half2_rn(o.z, o.w);
}

// ---------------------------------------------------------------------------
// loss: partials over 72 blocks (16 outputs each), then final reduce.
// ---------------------------------------------------------------------------
__global__ __launch_bounds__(128) void loss_part_kernel(
        const float* __restrict__ tgt, const float* __restrict__ Wh,
        const float* __restrict__ bh, const float* __restrict__ y,
        const float* __restrict__ w, float* __restrict__ part) {
    const int blk = blockIdx.x;           // 0..71
    const int tid = threadIdx.x;          // 128
    const int eo = tid >> 3, sub = tid & 7;   // 16 outputs x 8 threads
    const int e = blk*16 + eo;
    const int b = e / 144, j = e % 144;
    const float4* trow = (const float4*)(tgt + ((size_t)b*SS + SS-1)*DD);
    const float4* wr   = (const float4*)(Wh + (size_t)j*DD);
    float acc = 0.f;
    #pragma unroll 8
    for (int k = sub; k < 256; k += 8) {
        const float4 a = trow[k], v = wr[k];
        acc += a.x*v.x + a.y*v.y + a.z*v.z + a.w*v.w;
    }
    #pragma unroll
    for (int o = 4; o; o >>= 1) acc += __shfl_xor_sync(0xffffffffu, acc, o);
    __shared__ float red[16];
    if (sub == 0) {
        const float resid = y[b*144 + j] - w[((size_t)b*16 + 15)*144 + j];
        const float d = acc + bh[j] - resid;
        red[eo] = d*d;
    }
    __syncthreads();
    if (tid == 0) {
        float s = 0.f;
        #pragma unroll
        for (int i = 0; i < 16; i++) s += red[i];
        part[blk] = s;
    }
}
__global__ void loss_final_kernel(const float* __restrict__ part, float* __restrict__ out) {
    const int lane = threadIdx.x;   // 72 threads -> use 96, guard
    float v = (lane < 72) ? part[lane] : 0.f;
    #pragma unroll
    for (int o = 16; o; o >>= 1) v += __shfl_xor_sync(0xffffffffu, v, o);
    __shared__ float sh[4];
    if ((lane & 31) == 0) sh[lane >> 5] = v;
    __syncthreads();
    if (lane == 0) out[0] = (sh[0] + sh[1] + sh[2]) / 1152.f;
}

// ---------------------------------------------------------------------------
extern "C" void kernel_launch(void* const* d_in, const int* in_sizes, int n_in,
                              void* d_out, int out_size) {
    (void)in_sizes; (void)n_in; (void)out_size;
    const float* x      = (const float*)d_in[0];
    const float* w      = (const float*)d_in[1];
    const float* y      = (const float*)d_in[2];
    const float* W_nail = (const float*)d_in[3];
    const float* b_nail = (const float*)d_in[4];
    const float* W_cond = (const float*)d_in[5];
    const float* b_cond = (const float*)d_in[6];
    const float* Wqkv   = (const float*)d_in[7];
    const float* bqkv   = (const float*)d_in[8];
    const float* Wo     = (const float*)d_in[9];
    const float* bo     = (const float*)d_in[10];
    const float* ln1_g  = (const float*)d_in[11];
    const float* ln1_b  = (const float*)d_in[12];
    const float* ln2_g  = (const float*)d_in[13];
    const float* ln2_b  = (const float*)d_in[14];
    const float* W1     = (const float*)d_in[15];
    const float* b1     = (const float*)d_in[16];
    const float* W2     = (const float*)d_in[17];
    const float* b2     = (const float*)d_in[18];
    const float* W_ham  = (const float*)d_in[19];
    const float* b_ham  = (const float*)d_in[20];

    float *tgt, *mid, *dv, *pet, *wnt, *lpart;
    __half *qh, *xh, *gh, *wh;
    cudaGetSymbolAddress((void**)&tgt, g_tgt);
    cudaGetSymbolAddress((void**)&mid, g_mid);
    cudaGetSymbolAddress((void**)&qh,  g_qh);
    cudaGetSymbolAddress((void**)&xh,  g_xh);
    cudaGetSymbolAddress((void**)&gh,  g_gh);
    cudaGetSymbolAddress((void**)&wh,  g_wh);
    cudaGetSymbolAddress((void**)&dv,  g_div);
    cudaGetSymbolAddress((void**)&pet, g_pet);
    cudaGetSymbolAddress((void**)&wnt, g_wnt);
    cudaGetSymbolAddress((void**)&lpart, g_lpart);

    cudaFuncSetAttribute(gemm_f16<0>, cudaFuncAttributeMaxDynamicSharedMemorySize, GEMM_SMEM);
    cudaFuncSetAttribute(gemm_f16<1>, cudaFuncAttributeMaxDynamicSharedMemorySize, GEMM_SMEM);
    cudaFuncSetAttribute(gemm_f16<2>, cudaFuncAttributeMaxDynamicSharedMemorySize, GEMM_SMEM);
    cudaFuncSetAttribute(flash_hmma,  cudaFuncAttributeMaxDynamicSharedMemorySize, AT_SMEM);

    cvt_all_kernel<<<(N4_TOT+255)/256, 256>>>(Wqkv, Wo, W1, W2, wh);
    div_kernel<<<1, 512>>>(dv);
    pe_kernel<<<384, 256>>>(dv, pet);
    wnt_kernel<<<(63*DD+255)/256, 256>>>(W_nail, wnt);
    prep_x_kernel<<<dim3(8, 128), 256>>>(x, wnt, b_nail, dv, tgt, xh);
    prep_w_kernel<<<3072, 256>>>(w, W_cond, b_cond, pet, tgt, xh);

    for (int i = 0; i < NLAYERS; i++) {
        const __half* wq = wh + W_QKV_OFF + (size_t)i*3*DD*DD;
        const __half* wo = wh + W_O_OFF   + (size_t)i*DD*DD;
        const __half* w1 = wh + W_F1_OFF  + (size_t)i*FFD*DD;
        const __half* w2 = wh + W_F2_OFF  + (size_t)i*DD*FFD;
        const float* bqkv_i = bqkv + (size_t)i*3*DD;
        const float* bo_i   = bo   + (size_t)i*DD;
        const float* b1_i   = b1   + (size_t)i*FFD;
        const float* b2_i   = b2   + (size_t)i*DD;

        // qkv = x @ Wqkv^T + b  -> qh (fp16)
        gemm_f16<2><<<dim3(24, 56), 128, GEMM_SMEM>>>(xh, wq, bqkv_i, nullptr, qh, MTOT, 3*DD, DD);
        // attention -> xh (fp16)
        flash_hmma<<<dim3(14, BB*NH), 128, AT_SMEM>>>(qh, xh);
        // o-proj -> mid (fp32)
        gemm_f16<0><<<dim3(8, 56), 128, GEMM_SMEM>>>(xh, wo, bo_i, mid, nullptr, MTOT, DD, DD);
        // tgt = LN(tgt + o); writes xh
        add_ln_kernel<<<MTOT, 256>>>(tgt, mid, ln1_g + (size_t)i*DD, ln1_b + (size_t)i*DD, xh);
        // ff1 + gelu -> gh (fp16)
        gemm_f16<1><<<dim3(32, 56), 128, GEMM_SMEM>>>(xh, w1, b1_i, nullptr, gh, MTOT, FFD, DD);
        // ff2 -> mid (fp32)
        gemm_f16<0><<<dim3(8, 56), 128, GEMM_SMEM>>>(gh, w2, b2_i, mid, nullptr, MTOT, DD, FFD);
        // tgt = LN(tgt + ff); writes xh
        add_ln_kernel<<<MTOT, 256>>>(tgt, mid, ln2_g + (size_t)i*DD, ln2_b + (size_t)i*DD, xh);
    }

    loss_part_kernel<<<72, 128>>>(tgt, W_ham, b_ham, y, w, lpart);
    loss_final_kernel<<<1, 96>>>(lpart, (float*)d_out);
}

// round 17
// speedup vs baseline: 10.0210x; 1.0103x over previous
#include <cuda_runtime.h>
#include <cuda_fp16.h>
#include <math.h>
#include <stdint.h>

// Problem constants
#define BB 8
#define SS 896
#define LX 512
#define DD 1024
#define MTOT (BB*SS)    // 7168
#define NH 16
#define FFD 4096
#define NLAYERS 4

// fp16 weight buffer offsets (elements)
#define W_QKV_OFF 0
#define W_O_OFF   12582912
#define W_F1_OFF  16777216
#define W_F2_OFF  33554432
#define W_TOT     50331648

// Scratch (__device__ globals; allocation-free)
__device__ float  g_tgt[MTOT*DD];      // fp32 residual stream
__device__ float  g_mid[MTOT*DD];      // o-proj / ff2 fp32 outputs
__device__ __half g_qh[MTOT*3*DD];     // qkv fp16
__device__ __half g_xh[MTOT*DD];       // fp16 activation (GEMM A operand)
__device__ __half g_gh[MTOT*FFD];      // fp16 gelu intermediate
__device__ __half g_wh[W_TOT];         // fp16 weights
__device__ float  g_pet[384*DD];       // exact PE for pos 512..895
__device__ float  g_wnt[63*DD];        // W_nail transposed [63][1024]
__device__ float  g_lpart[72];         // loss partials

#define CDIV_CONST (-0.0067458547646309937f)   // -log(1000)/1024

__device__ __forceinline__ uint32_t smem_u32(const void* p) {
    uint32_t a;
    asm("{ .reg .u64 t; cvta.to.shared.u64 t, %1; cvt.u32.u64 %0, t; }" : "=r"(a) : "l"(p));
    return a;
}

// ---------------------------------------------------------------------------
// Fused weight convert fp32 -> fp16 (all four weight tensors, one launch)
// ---------------------------------------------------------------------------
#define N4_QKV 3145728
#define N4_O   1048576
#define N4_F1  4194304
#define N4_F2  4194304
#define N4_TOT (N4_QKV+N4_O+N4_F1+N4_F2)

__global__ void cvt_all_kernel(const float* __restrict__ wq, const float* __restrict__ wo,
                               const float* __restrict__ w1, const float* __restrict__ w2,
                               __half* __restrict__ d) {
    int i = blockIdx.x * blockDim.x + threadIdx.x;
    if (i >= N4_TOT) return;
    const float* s; size_t off;
    if (i < N4_QKV)                 { s = wq; off = i;                       }
    else if (i < N4_QKV+N4_O)       { s = wo; off = i - N4_QKV;             }
    else if (i < N4_QKV+N4_O+N4_F1) { s = w1; off = i - (N4_QKV+N4_O);      }
    else                            { s = w2; off = i - (N4_QKV+N4_O+N4_F1);}
    float4 v = ((const float4*)s)[off];
    __half2 h0 = __floats2half2_rn(v.x, v.y);
    __half2 h1 = __floats2half2_rn(v.z, v.w);
    uint2 u;
    u.x = *(uint32_t*)&h0;
    u.y = *(uint32_t*)&h1;
    ((uint2*)d)[i] = u;
}

// ---------------------------------------------------------------------------
// Tables
// ---------------------------------------------------------------------------
__global__ void pe_kernel(float* __restrict__ pet) {
    const int pos = 512 + blockIdx.x;     // 512..895
    const int tid = threadIdx.x;          // 256
    #pragma unroll
    for (int it = 0; it < 4; it++) {
        const int d = tid + it*256;
        const float ang = (float)pos * expf((float)(d >> 1) * CDIV_CONST);
        pet[blockIdx.x*DD + d] = (d & 1) ? cosf(ang) : sinf(ang);
    }
}
__global__ void wnt_kernel(const float* __restrict__ Wn, float* __restrict__ WnT) {
    int i = blockIdx.x * blockDim.x + threadIdx.x;   // 0..64511
    if (i >= 63*DD) return;
    int d = i / 63, k = i % 63;
    WnT[k*DD + d] = Wn[i];
}

// ---------------------------------------------------------------------------
// fp16 HMMA GEMM: C = A @ W^T + bias.
// 128x128 CTA tile, 4 warps (2x2), 64x64 warp tile, BK=64, 3-stage cp.async,
// fragment-level software pipelining, 2 CTAs/SM.
// MODE 0: fp32 out. MODE 1: GELU, fp16 out. MODE 2: fp16 out.
// ---------------------------------------------------------------------------
#define GEMM_SMEM (3*32768)

template<int MODE>
__global__ __launch_bounds__(128, 2) void gemm_f16(
        const __half* __restrict__ A, const __half* __restrict__ B,
        const float* __restrict__ bias, float* __restrict__ Cf,
        __half* __restrict__ Ch, int M, int N, int K) {
    extern __shared__ char smem[];
    const uint32_t sb = smem_u32(smem);
    const int tid = threadIdx.x, lane = tid & 31, wid = tid >> 5;
    const int wm = wid & 1, wn = wid >> 1;          // 2 x 2 warp grid
    const int m0 = blockIdx.y * 128, n0 = blockIdx.x * 128;

    float acc[4][8][4];
    #pragma unroll
    for (int a = 0; a < 4; a++)
        #pragma unroll
        for (int b = 0; b < 8; b++)
            #pragma unroll
            for (int cc = 0; cc < 4; cc++) acc[a][b][cc] = 0.f;

    auto load_chunk = [&](int c, int s) {
        const int k0 = c << 6;
        const uint32_t stg = sb + s * 32768;
        #pragma unroll
        for (int i = 0; i < 8; i++) {
            int u = tid + (i << 7);
            int row = u >> 3, cc = u & 7;
            uint32_t dA = stg + row * 128 + ((cc ^ (row & 7)) << 4);
            const void* gA = A + (size_t)(m0 + row) * K + k0 + cc * 8;
            asm volatile("cp.async.cg.shared.global [%0], [%1], 16;" :: "r"(dA), "l"(gA));
        }
        #pragma unroll
        for (int i = 0; i < 8; i++) {
            int u = tid + (i << 7);
            int row = u >> 3, cc = u & 7;
            uint32_t dB = stg + 16384 + row * 128 + ((cc ^ (row & 7)) << 4);
            const void* gB = B + (size_t)(n0 + row) * K + k0 + cc * 8;
            asm volatile("cp.async.cg.shared.global [%0], [%1], 16;" :: "r"(dB), "l"(gB));
        }
        asm volatile("cp.async.commit_group;" ::: "memory");
    };

    const int NC = K >> 6;
    load_chunk(0, 0);
    load_chunk(1, 1);
    int s3 = 0;

    const int ac = (lane >> 4), bc = ((lane >> 3) & 1), lx = lane & 7;
    uint32_t af[2][4][4], bf[2][8][2];

    for (int c = 0; c < NC; c++) {
        if (c + 1 < NC) asm volatile("cp.async.wait_group 1;" ::: "memory");
        else            asm volatile("cp.async.wait_group 0;" ::: "memory");
        __syncthreads();
        if (c + 2 < NC) {
            int sn = s3 + 2; if (sn >= 3) sn -= 3;
            load_chunk(c + 2, sn);
        }

        const uint32_t stg = sb + s3 * 32768;
        const uint32_t arow = stg + (wm * 64 + (lane & 15)) * 128;
        const uint32_t brow = stg + 16384
                            + (wn * 64 + ((lane >> 4) << 3) + (lane & 7)) * 128;

        auto ldfrag = [&](int ks, int pb) {
            const uint32_t axor = (uint32_t)(((2 * ks + ac) ^ lx) << 4);
            const uint32_t bxor = (uint32_t)(((2 * ks + bc) ^ lx) << 4);
            #pragma unroll
            for (int mt = 0; mt < 4; mt++) {
                asm volatile("ldmatrix.sync.aligned.m8n8.x4.shared.b16 {%0,%1,%2,%3}, [%4];"
                    : "=r"(af[pb][mt][0]), "=r"(af[pb][mt][1]),
                      "=r"(af[pb][mt][2]), "=r"(af[pb][mt][3])
                    : "r"(arow + mt * 2048 + axor));
            }
            #pragma unroll
            for (int p = 0; p < 4; p++) {
                uint32_t r0, r1, r2, r3;
                asm volatile("ldmatrix.sync.aligned.m8n8.x4.shared.b16 {%0,%1,%2,%3}, [%4];"
                    : "=r"(r0), "=r"(r1), "=r"(r2), "=r"(r3)
                    : "r"(brow + p * 2048 + bxor));
                bf[pb][2*p][0] = r0; bf[pb][2*p][1] = r1;
                bf[pb][2*p+1][0] = r2; bf[pb][2*p+1][1] = r3;
            }
        };

        ldfrag(0, 0);
        #pragma unroll
        for (int ks = 0; ks < 4; ks++) {
            const int cur = ks & 1;
            if (ks < 3) ldfrag(ks + 1, cur ^ 1);
            #pragma unroll
            for (int mt = 0; mt < 4; mt++)
                #pragma unroll
                for (int nt = 0; nt < 8; nt++)
                    asm volatile(
                        "mma.sync.aligned.m16n8k16.row.col.f32.f16.f16.f32 "
                        "{%0,%1,%2,%3}, {%4,%5,%6,%7}, {%8,%9}, {%0,%1,%2,%3};"
                        : "+f"(acc[mt][nt][0]), "+f"(acc[mt][nt][1]),
                          "+f"(acc[mt][nt][2]), "+f"(acc[mt][nt][3])
                        : "r"(af[cur][mt][0]), "r"(af[cur][mt][1]),
                          "r"(af[cur][mt][2]), "r"(af[cur][mt][3]),
                          "r"(bf[cur][nt][0]), "r"(bf[cur][nt][1]));
        }
        s3++; if (s3 == 3) s3 = 0;
    }
    __syncthreads();

    // Epilogue (register -> global, fused bias/GELU/fp16)
    #pragma unroll
    for (int mt = 0; mt < 4; mt++) {
        const int m = m0 + wm * 64 + mt * 16 + (lane >> 2);
        #pragma unroll
        for (int nt = 0; nt < 8; nt++) {
            const int n = n0 + wn * 64 + nt * 8 + (lane & 3) * 2;
            const float b0 = bias[n], b1 = bias[n + 1];
            float v0 = acc[mt][nt][0] + b0, v1 = acc[mt][nt][1] + b1;
            float v2 = acc[mt][nt][2] + b0, v3 = acc[mt][nt][3] + b1;
            if (MODE == 1) {
                v0 = 0.5f * v0 * (1.0f + erff(v0 * 0.70710678118654752f));
                v1 = 0.5f * v1 * (1.0f + erff(v1 * 0.70710678118654752f));
                v2 = 0.5f * v2 * (1.0f + erff(v2 * 0.70710678118654752f));
                v3 = 0.5f * v3 * (1.0f + erff(v3 * 0.70710678118654752f));
            }
            if (MODE == 0) {
                float2 f01, f23;
                f01.x = v0; f01.y = v1; f23.x = v2; f23.y = v3;
                *(float2*)(Cf + (size_t)m * N + n)       = f01;
                *(float2*)(Cf + (size_t)(m + 8) * N + n) = f23;
            } else {
                *(__half2*)(Ch + (size_t)m * N + n)       = __floats2half2_rn(v0, v1);
                *(__half2*)(Ch + (size_t)(m + 8) * N + n) = __floats2half2_rn(v2, v3);
            }
        }
    }
}

// ---------------------------------------------------------------------------
// prep_x: x-region rows (4096). Tiled: 32 rows x 128 cols per block.
// ---------------------------------------------------------------------------
__global__ __launch_bounds__(256) void prep_x_kernel(
        const float* __restrict__ x, const float* __restrict__ WnT,
        const float* __restrict__ bn,
        float* __restrict__ tgt, __half* __restrict__ xh) {
    const int d0 = blockIdx.x * 128;
    const int rt = blockIdx.y;
    const int tid = threadIdx.x;
    __shared__ float f[32][64];
    __shared__ float sh_t[32];
    const float rs = 0.9999500037496877f;

    #pragma unroll
    for (int i = 0; i < 8; i++) {
        const int id = tid + i*256;
        const int r = id >> 6, c = id & 63;
        float v = x[(size_t)(rt*32 + r)*64 + c];
        if (isnan(v)) v = 0.f;
        if (c == 0) sh_t[r] = v;
        else {
            v *= rs;
            f[r][c-1] = fminf(5.f, fmaxf(-5.f, v));
        }
    }
    __syncthreads();

    const int dloc = tid & 127, rh = tid >> 7;
    const int d = d0 + dloc;
    float acc[16];
    #pragma unroll
    for (int r = 0; r < 16; r++) acc[r] = 0.f;
    #pragma unroll 7
    for (int k = 0; k < 63; k++) {
        const float wv = WnT[k*DD + d];
        #pragma unroll
        for (int r = 0; r < 16; r++) acc[r] += f[rh*16 + r][k] * wv;
    }
    const float bnv = bn[d];
    const float dvv = expf((float)(d >> 1) * CDIV_CONST);
    const int odd = d & 1;
    #pragma unroll
    for (int r = 0; r < 16; r++) {
        const int xrow = rt*32 + rh*16 + r;
        const float ang = sh_t[rh*16 + r] * dvv;
        const float pe = odd ? __cosf(ang) : __sinf(ang);
        const float v = acc[r] + bnv + pe;
        const int b = xrow >> 9, s = xrow & 511;
        const size_t off = (size_t)(b*SS + s)*DD + d;
        tgt[off] = v;
        xh[off] = __float2half(v);
    }
}

// ---------------------------------------------------------------------------
// prep_w: w-region rows (3072), K=6.
// ---------------------------------------------------------------------------
__global__ void prep_w_kernel(const float* __restrict__ w,
                              const float* __restrict__ Wc, const float* __restrict__ bc,
                              const float* __restrict__ pet,
                              float* __restrict__ tgt, __half* __restrict__ xh) {
    const int blk = blockIdx.x;
    const int b = blk / 384, j = blk % 384;
    const int row = b*SS + LX + j;
    const int tid = threadIdx.x;
    __shared__ float f[6];
    const float rs = 0.9999500037496877f;
    if (tid < 6) {
        float v = w[((size_t)b*384 + j)*6 + tid];
        if (isnan(v)) v = 0.f;
        v *= rs;
        f[tid] = fminf(5.f, fmaxf(-5.f, v));
    }
    __syncthreads();
    #pragma unroll
    for (int it = 0; it < 4; it++) {
        const int d = tid + it*256;
        float acc = bc[d];
        const float* wr = Wc + (size_t)d*6;
        #pragma unroll
        for (int k = 0; k < 6; k++) acc += f[k]*wr[k];
        acc += pet[(size_t)j*DD + d];
        tgt[(size_t)row*DD + d] = acc;
        xh[(size_t)row*DD + d] = __float2half(acc);
    }
}

// ---------------------------------------------------------------------------
// HMMA flash attention (unchanged).
// ---------------------------------------------------------------------------
#define AT_SMEM (8192*5)

__global__ __launch_bounds__(128) void flash_hmma(
        const __half* __restrict__ qkv, __half* __restrict__ xh) {
    extern __shared__ char smem[];
    const uint32_t sb = smem_u32(smem);
    const int q0 = blockIdx.x * 64;
    const int bh = blockIdx.y;
    const int b = bh >> 4, h = bh & 15;
    const int tid = threadIdx.x, lane = tid & 31, wid = tid >> 5;
    const __half* base = qkv + (size_t)b * SS * 3072;

    #pragma unroll
    for (int i = 0; i < 4; i++) {
        const int id = tid + i*128;
        const int row = id >> 3, c = id & 7;
        const uint32_t dst = sb + row*128 + ((c ^ (row & 7)) << 4);
        const void* src = base + (size_t)(q0 + row)*3072 + h*64 + c*8;
        asm volatile("cp.async.cg.shared.global [%0], [%1], 16;" :: "r"(dst), "l"(src));
    }
    auto loadKV = [&](int kt, int s) {
        const int c0 = kt * 64;
        const uint32_t stg = sb + 8192 + s*16384;
        #pragma unroll
        for (int i = 0; i < 4; i++) {
            const int id = tid + i*128;
            const int row = id >> 3, c = id & 7;
            const uint32_t sw = ((c ^ (row & 7)) << 4);
            const void* srcK = base + (size_t)(c0 + row)*3072 + 1024 + h*64 + c*8;
            const void* srcV = base + (size_t)(c0 + row)*3072 + 2048 + h*64 + c*8;
            asm volatile("cp.async.cg.shared.global [%0], [%1], 16;" :: "r"(stg + row*128 + sw), "l"(srcK));
            asm volatile("cp.async.cg.shared.global [%0], [%1], 16;" :: "r"(stg + 8192 + row*128 + sw), "l"(srcV));
        }
        asm volatile("cp.async.commit_group;" ::: "memory");
    };
    loadKV(0, 0);

    const int ntiles = (q0 >= 512) ? (q0/64 + 1) : 8;

    float o[8][4];
    #pragma unroll
    for (int u = 0; u < 8; u++)
        #pragma unroll
        for (int e = 0; e < 4; e++) o[u][e] = 0.f;
    float m0 = -1e30f, m1 = -1e30f, l0 = 0.f, l1 = 0.f;
    uint32_t qa[4][4];

    const int lx = lane & 7;
    const int rbase = q0 + (wid << 4) + (lane >> 2);

    for (int kt = 0; kt < ntiles; kt++) {
        const int s = kt & 1;
        asm volatile("cp.async.wait_group 0;" ::: "memory");
        __syncthreads();
        if (kt == 0) {
            const uint32_t arow = sb + ((wid << 4) + (lane & 15)) * 128;
            const int ac = lane >> 4;
            #pragma unroll
            for (int ks = 0; ks < 4; ks++) {
                asm volatile("ldmatrix.sync.aligned.m8n8.x4.shared.b16 {%0,%1,%2,%3}, [%4];"
                    : "=r"(qa[ks][0]), "=r"(qa[ks][1]), "=r"(qa[ks][2]), "=r"(qa[ks][3])
                    : "r"(arow + ((uint32_t)((2*ks + ac) ^ lx) << 4)));
            }
        }
        if (kt + 1 < ntiles) loadKV(kt + 1, s ^ 1);

        const uint32_t stg = sb + 8192 + s*16384;
        float sc[8][4];
        #pragma unroll
        for (int u = 0; u < 8; u++)
            #pragma unroll
            for (int e = 0; e < 4; e++) sc[u][e] = 0.f;
        {
            const uint32_t brow = stg + (((lane >> 4) << 3) + (lane & 7)) * 128;
            const int bc = (lane >> 3) & 1;
            #pragma unroll
            for (int ks = 0; ks < 4; ks++) {
                const uint32_t bxor = (uint32_t)(((2*ks + bc) ^ lx) << 4);
                #pragma unroll
                for (int p = 0; p < 4; p++) {
                    uint32_t r0, r1, r2, r3;
                    asm volatile("ldmatrix.sync.aligned.m8n8.x4.shared.b16 {%0,%1,%2,%3}, [%4];"
                        : "=r"(r0), "=r"(r1), "=r"(r2), "=r"(r3)
                        : "r"(brow + p * 2048 + bxor));
                    asm volatile(
                        "mma.sync.aligned.m16n8k16.row.col.f32.f16.f16.f32 "
                        "{%0,%1,%2,%3}, {%4,%5,%6,%7}, {%8,%9}, {%0,%1,%2,%3};"
                        : "+f"(sc[2*p][0]), "+f"(sc[2*p][1]), "+f"(sc[2*p][2]), "+f"(sc[2*p][3])
                        : "r"(qa[ks][0]), "r"(qa[ks][1]), "r"(qa[ks][2]), "r"(qa[ks][3]),
                          "r"(r0), "r"(r1));
                    asm volatile(
                        "mma.sync.aligned.m16n8k16.row.col.f32.f16.f16.f32 "
                        "{%0,%1,%2,%3}, {%4,%5,%6,%7}, {%8,%9}, {%0,%1,%2,%3};"
                        : "+f"(sc[2*p+1][0]), "+f"(sc[2*p+1][1]), "+f"(sc[2*p+1][2]), "+f"(sc[2*p+1][3])
                        : "r"(qa[ks][0]), "r"(qa[ks][1]), "r"(qa[ks][2]), "r"(qa[ks][3]),
                          "r"(r2), "r"(r3));
                }
            }
        }
        const int c0 = kt * 64;
        const bool needMask = (c0 + 63 >= LX) && (c0 + 63 > q0);
        #pragma unroll
        for (int u = 0; u < 8; u++) {
            #pragma unroll
            for (int e = 0; e < 4; e++) {
                float v = sc[u][e] * 0.125f;
                if (needMask) {
                    const int c = c0 + u*8 + ((lane & 3) << 1) + (e & 1);
                    const int r = rbase + ((e >> 1) << 3);
                    if (c >= LX && c > r) v = -1e30f;
                }
                sc[u][e] = v;
            }
        }
        float rm0 = -1e30f, rm1 = -1e30f;
        #pragma unroll
        for (int u = 0; u < 8; u++) {
            rm0 = fmaxf(rm0, fmaxf(sc[u][0], sc[u][1]));
            rm1 = fmaxf(rm1, fmaxf(sc[u][2], sc[u][3]));
        }
        rm0 = fmaxf(rm0, __shfl_xor_sync(0xffffffffu, rm0, 1));
        rm0 = fmaxf(rm0, __shfl_xor_sync(0xffffffffu, rm0, 2));
        rm1 = fmaxf(rm1, __shfl_xor_sync(0xffffffffu, rm1, 1));
        rm1 = fmaxf(rm1, __shfl_xor_sync(0xffffffffu, rm1, 2));
        const float mn0 = fmaxf(m0, rm0), mn1 = fmaxf(m1, rm1);
        const float al0 = __expf(m0 - mn0), al1 = __expf(m1 - mn1);
        m0 = mn0; m1 = mn1;
        float ps0 = 0.f, ps1 = 0.f;
        #pragma unroll
        for (int u = 0; u < 8; u++) {
            float e0 = (sc[u][0] > -1e29f) ? __expf(sc[u][0] - mn0) : 0.f;
            float e1 = (sc[u][1] > -1e29f) ? __expf(sc[u][1] - mn0) : 0.f;
            float e2 = (sc[u][2] > -1e29f) ? __expf(sc[u][2] - mn1) : 0.f;
            float e3 = (sc[u][3] > -1e29f) ? __expf(sc[u][3] - mn1) : 0.f;
            sc[u][0] = e0; sc[u][1] = e1; sc[u][2] = e2; sc[u][3] = e3;
            ps0 += e0 + e1; ps1 += e2 + e3;
        }
        ps0 += __shfl_xor_sync(0xffffffffu, ps0, 1);
        ps0 += __shfl_xor_sync(0xffffffffu, ps0, 2);
        ps1 += __shfl_xor_sync(0xffffffffu, ps1, 1);
        ps1 += __shfl_xor_sync(0xffffffffu, ps1, 2);
        l0 = l0 * al0 + ps0;
        l1 = l1 * al1 + ps1;
        #pragma unroll
        for (int u = 0; u < 8; u++) {
            o[u][0] *= al0; o[u][1] *= al0; o[u][2] *= al1; o[u][3] *= al1;
        }
        const uint32_t vstg = stg + 8192;
        const int vrow_l = lane & 15;
        #pragma unroll
        for (int t = 0; t < 4; t++) {
            uint32_t pa0, pa1, pa2, pa3;
            {
                __half2 h0 = __floats2half2_rn(sc[2*t][0],   sc[2*t][1]);
                __half2 h1 = __floats2half2_rn(sc[2*t][2],   sc[2*t][3]);
                __half2 h2 = __floats2half2_rn(sc[2*t+1][0], sc[2*t+1][1]);
                __half2 h3 = __floats2half2_rn(sc[2*t+1][2], sc[2*t+1][3]);
                pa0 = *(uint32_t*)&h0; pa1 = *(uint32_t*)&h1;
                pa2 = *(uint32_t*)&h2; pa3 = *(uint32_t*)&h3;
            }
            const int vrow = t*16 + vrow_l;
            const uint32_t vbase = vstg + vrow*128;
            #pragma unroll
            for (int up = 0; up < 4; up++) {
                uint32_t v0, v1, v2, v3;
                const uint32_t chunk = (uint32_t)(2*up + (lane >> 4));
                asm volatile("ldmatrix.sync.aligned.m8n8.x4.trans.shared.b16 {%0,%1,%2,%3}, [%4];"
                    : "=r"(v0), "=r"(v1), "=r"(v2), "=r"(v3)
                    : "r"(vbase + ((chunk ^ (uint32_t)(vrow & 7)) << 4)));
                asm volatile(
                    "mma.sync.aligned.m16n8k16.row.col.f32.f16.f16.f32 "
                    "{%0,%1,%2,%3}, {%4,%5,%6,%7}, {%8,%9}, {%0,%1,%2,%3};"
                    : "+f"(o[2*up][0]), "+f"(o[2*up][1]), "+f"(o[2*up][2]), "+f"(o[2*up][3])
                    : "r"(pa0), "r"(pa1), "r"(pa2), "r"(pa3), "r"(v0), "r"(v1));
                asm volatile(
                    "mma.sync.aligned.m16n8k16.row.col.f32.f16.f16.f32 "
                    "{%0,%1,%2,%3}, {%4,%5,%6,%7}, {%8,%9}, {%0,%1,%2,%3};"
                    : "+f"(o[2*up+1][0]), "+f"(o[2*up+1][1]), "+f"(o[2*up+1][2]), "+f"(o[2*up+1][3])
                    : "r"(pa0), "r"(pa1), "r"(pa2), "r"(pa3), "r"(v2), "r"(v3));
            }
        }
    }

    const float inv0 = 1.f / l0, inv1 = 1.f / l1;
    const int orow0 = b*SS + q0 + (wid << 4) + (lane >> 2);
    const int colb = h*64 + ((lane & 3) << 1);
    #pragma unroll
    for (int u = 0; u < 8; u++) {
        *(__half2*)(xh + (size_t)orow0*DD + colb + u*8) =
            __floats2half2_rn(o[u][0]*inv0, o[u][1]*inv0);
        *(__half2*)(xh + (size_t)(orow0 + 8)*DD + colb + u*8) =
            __floats2half2_rn(o[u][2]*inv1, o[u][3]*inv1);
    }
}

// ---------------------------------------------------------------------------
// x = LayerNorm(x + r)*g + b (in-place, fp32) + fp16 copy
// ---------------------------------------------------------------------------
__global__ __launch_bounds__(256) void add_ln_kernel(
        float* __restrict__ x, const float* __restrict__ r,
        const float* __restrict__ g, const float* __restrict__ bt,
        __half* __restrict__ xh) {
    const int row = blockIdx.x;
    const int tid = threadIdx.x;
    const size_t off = (size_t)row*DD + tid*4;
    float4 xv = *(float4*)(x + off);
    const float4 rv = *(const float4*)(r + off);
    xv.x += rv.x; xv.y += rv.y; xv.z += rv.z; xv.w += rv.w;
    float s  = xv.x + xv.y + xv.z + xv.w;
    float s2 = xv.x*xv.x + xv.y*xv.y + xv.z*xv.z + xv.w*xv.w;
    __shared__ float sh[16];
    #pragma unroll
    for (int o = 16; o; o >>= 1) {
        s  += __shfl_xor_sync(0xffffffffu, s,  o);
        s2 += __shfl_xor_sync(0xffffffffu, s2, o);
    }
    const int warp = tid >> 5, lane = tid & 31;
    if (lane == 0) { sh[warp] = s; sh[warp+8] = s2; }
    __syncthreads();
    if (tid < 32) {
        float a  = (lane < 8) ? sh[lane]   : 0.f;
        float a2 = (lane < 8) ? sh[lane+8] : 0.f;
        #pragma unroll
        for (int o = 4; o; o >>= 1) {
            a  += __shfl_xor_sync(0xffffffffu, a,  o);
            a2 += __shfl_xor_sync(0xffffffffu, a2, o);
        }
        if (lane == 0) { sh[0] = a; sh[1] = a2; }
    }
    __syncthreads();
    const float mean = sh[0] * (1.f/1024.f);
    const float var  = sh[1] * (1.f/1024.f) - mean*mean;
    const float rstd = 1.f / sqrtf(var + 1e-5f);
    const float4 gv = *(const float4*)(g  + tid*4);
    const float4 bv = *(const float4*)(bt + tid*4);
    float4 o;
    o.x = (xv.x - mean)*rstd*gv.x + bv.x;
    o.y = (xv.y - mean)*rstd*gv.y + bv.y;
    o.z = (xv.z - mean)*rstd*gv.z + bv.z;
    o.w = (xv.w - mean)*rstd*gv.w + bv.w;
    *(float4*)(x + off) = o;
    *(__half2*)(xh + off)     = __floats2half2_rn(o.x, o.y);
    *(__half2*)(xh + off + 2) = __floats2half2_rn(o.z, o.w);
}

// ---------------------------------------------------------------------------
// loss: partials over 72 blocks (16 outputs each), then final reduce.
// ---------------------------------------------------------------------------
__global__ __launch_bounds__(128) void loss_part_kernel(
        const float* __restrict__ tgt, const float* __restrict__ Wh,
        const float* __restrict__ bh, const float* __restrict__ y,
        const float* __restrict__ w, float* __restrict__ part) {
    const int blk = blockIdx.x;           // 0..71
    const int tid = threadIdx.x;          // 128
    const int eo = tid >> 3, sub = tid & 7;
    const int e = blk*16 + eo;
    const int b = e / 144, j = e % 144;
    const float4* trow = (const float4*)(tgt + ((size_t)b*SS + SS-1)*DD);
    const float4* wr   = (const float4*)(Wh + (size_t)j*DD);
    float acc = 0.f;
    #pragma unroll 8
    for (int k = sub; k < 256; k += 8) {
        const float4 a = trow[k], v = wr[k];
        acc += a.x*v.x + a.y*v.y + a.z*v.z + a.w*v.w;
    }
    #pragma unroll
    for (int o = 4; o; o >>= 1) acc += __shfl_xor_sync(0xffffffffu, acc, o);
    __shared__ float red[16];
    if (sub == 0) {
        const float resid = y[b*144 + j] - w[((size_t)b*16 + 15)*144 + j];
        const float d = acc + bh[j] - resid;
        red[eo] = d*d;
    }
    __syncthreads();
    if (tid == 0) {
        float s = 0.f;
        #pragma unroll
        for (int i = 0; i < 16; i++) s += red[i];
        part[blk] = s;
    }
}
__global__ void loss_final_kernel(const float* __restrict__ part, float* __restrict__ out) {
    const int lane = threadIdx.x;
    float v = (lane < 72) ? part[lane] : 0.f;
    #pragma unroll
    for (int o = 16; o; o >>= 1) v += __shfl_xor_sync(0xffffffffu, v, o);
    __shared__ float sh[4];
    if ((lane & 31) == 0) sh[lane >> 5] = v;
    __syncthreads();
    if (lane == 0) out[0] = (sh[0] + sh[1] + sh[2]) / 1152.f;
}

// ---------------------------------------------------------------------------
extern "C" void kernel_launch(void* const* d_in, const int* in_sizes, int n_in,
                              void* d_out, int out_size) {
    (void)in_sizes; (void)n_in; (void)out_size;
    const float* x      = (const float*)d_in[0];
    const float* w      = (const float*)d_in[1];
    const float* y      = (const float*)d_in[2];
    const float* W_nail = (const float*)d_in[3];
    const float* b_nail = (const float*)d_in[4];
    const float* W_cond = (const float*)d_in[5];
    const float* b_cond = (const float*)d_in[6];
    const float* Wqkv   = (const float*)d_in[7];
    const float* bqkv   = (const float*)d_in[8];
    const float* Wo     = (const float*)d_in[9];
    const float* bo     = (const float*)d_in[10];
    const float* ln1_g  = (const float*)d_in[11];
    const float* ln1_b  = (const float*)d_in[12];
    const float* ln2_g  = (const float*)d_in[13];
    const float* ln2_b  = (const float*)d_in[14];
    const float* W1     = (const float*)d_in[15];
    const float* b1     = (const float*)d_in[16];
    const float* W2     = (const float*)d_in[17];
    const float* b2     = (const float*)d_in[18];
    const float* W_ham  = (const float*)d_in[19];
    const float* b_ham  = (const float*)d_in[20];

    float *tgt, *mid, *pet, *wnt, *lpart;
    __half *qh, *xh, *gh, *wh;
    cudaGetSymbolAddress((void**)&tgt, g_tgt);
    cudaGetSymbolAddress((void**)&mid, g_mid);
    cudaGetSymbolAddress((void**)&qh,  g_qh);
    cudaGetSymbolAddress((void**)&xh,  g_xh);
    cudaGetSymbolAddress((void**)&gh,  g_gh);
    cudaGetSymbolAddress((void**)&wh,  g_wh);
    cudaGetSymbolAddress((void**)&pet, g_pet);
    cudaGetSymbolAddress((void**)&wnt, g_wnt);
    cudaGetSymbolAddress((void**)&lpart, g_lpart);

    cudaFuncSetAttribute(gemm_f16<0>, cudaFuncAttributeMaxDynamicSharedMemorySize, GEMM_SMEM);
    cudaFuncSetAttribute(gemm_f16<1>, cudaFuncAttributeMaxDynamicSharedMemorySize, GEMM_SMEM);
    cudaFuncSetAttribute(gemm_f16<2>, cudaFuncAttributeMaxDynamicSharedMemorySize, GEMM_SMEM);
    cudaFuncSetAttribute(flash_hmma,  cudaFuncAttributeMaxDynamicSharedMemorySize, AT_SMEM);

    cvt_all_kernel<<<(N4_TOT+255)/256, 256>>>(Wqkv, Wo, W1, W2, wh);
    pe_kernel<<<384, 256>>>(pet);
    wnt_kernel<<<(63*DD+255)/256, 256>>>(W_nail, wnt);
    prep_x_kernel<<<dim3(8, 128), 256>>>(x, wnt, b_nail, tgt, xh);
    prep_w_kernel<<<3072, 256>>>(w, W_cond, b_cond, pet, tgt, xh);

    for (int i = 0; i < NLAYERS; i++) {
        const __half* wq = wh + W_QKV_OFF + (size_t)i*3*DD*DD;
        const __half* wo = wh + W_O_OFF   + (size_t)i*DD*DD;
        const __half* w1 = wh + W_F1_OFF  + (size_t)i*FFD*DD;
        const __half* w2 = wh + W_F2_OFF  + (size_t)i*DD*FFD;
        const float* bqkv_i = bqkv + (size_t)i*3*DD;
        const float* bo_i   = bo   + (size_t)i*DD;
        const float* b1_i   = b1   + (size_t)i*FFD;
        const float* b2_i   = b2   + (size_t)i*DD;

        // qkv = x @ Wqkv^T + b  -> qh (fp16)
        gemm_f16<2><<<dim3(24, 56), 128, GEMM_SMEM>>>(xh, wq, bqkv_i, nullptr, qh, MTOT, 3*DD, DD);
        // attention -> xh (fp16)
        flash_hmma<<<dim3(14, BB*NH), 128, AT_SMEM>>>(qh, xh);
        // o-proj -> mid (fp32)
        gemm_f16<0><<<dim3(8, 56), 128, GEMM_SMEM>>>(xh, wo, bo_i, mid, nullptr, MTOT, DD, DD);
        // tgt = LN(tgt + o); writes xh
        add_ln_kernel<<<MTOT, 256>>>(tgt, mid, ln1_g + (size_t)i*DD, ln1_b + (size_t)i*DD, xh);
        // ff1 + gelu -> gh (fp16)
        gemm_f16<1><<<dim3(32, 56), 128, GEMM_SMEM>>>(xh, w1, b1_i, nullptr, gh, MTOT, FFD, DD);
        // ff2 -> mid (fp32)
        gemm_f16<0><<<dim3(8, 56), 128, GEMM_SMEM>>>(gh, w2, b2_i, mid, nullptr, MTOT, DD, FFD);
        // tgt = LN(tgt + ff); writes xh
        add_ln_kernel<<<MTOT, 256>>>(tgt, mid, ln2_g + (size_t)i*DD, ln2_b + (size_t)i*DD, xh);
    }

    loss_part_kernel<<<72, 128>>>(tgt, W_ham, b_ham, y, w, lpart);
    loss_final_kernel<<<1, 96>>>(lpart, (float*)d_out);
}